// round 7
// baseline (speedup 1.0000x reference)
#include <cuda_runtime.h>
#include <cuda_fp16.h>
#include <cstdint>
#include <math.h>

// ---------------------------------------------------------------------------
// Problem constants
// ---------------------------------------------------------------------------
#define NB   256
#define TT   64
#define INW  150
#define INWP 160
#define HH   1024
#define G3   (3*HH)
#define H2   (2*HH)
#define NT   (NB*TT)
#define NCLS 60

// ---------------------------------------------------------------------------
// Device scratch
// ---------------------------------------------------------------------------
__device__ __half g_xn   [(size_t)NT * INWP];
__device__ __half g_wih0h[(size_t)2 * G3 * INWP];
__device__ __half g_wih1h[(size_t)2 * G3 * H2];
__device__ __half g_wih2h[(size_t)2 * G3 * H2];
__device__ __half g_whhh [3][(size_t)2 * G3 * HH];
__device__ float  g_gi   [2][(size_t)NT * G3];
__device__ __half g_bufAh[(size_t)NT * H2];
__device__ __half g_bufBh[(size_t)NT * H2];
__device__ float  g_h    [2][(size_t)NB * HH];
__device__ __half g_hh   [2][(size_t)NB * HH];
__device__ float  g_bn   [2 * INW];

// ---------------------------------------------------------------------------
// PTX helpers
// ---------------------------------------------------------------------------
__device__ __forceinline__ void mma_f16(float* d,
                                        uint32_t a0, uint32_t a1, uint32_t a2, uint32_t a3,
                                        uint32_t b0, uint32_t b1)
{
    asm volatile(
        "mma.sync.aligned.m16n8k16.row.col.f32.f16.f16.f32 "
        "{%0,%1,%2,%3}, {%4,%5,%6,%7}, {%8,%9}, {%0,%1,%2,%3};"
        : "+f"(d[0]), "+f"(d[1]), "+f"(d[2]), "+f"(d[3])
        : "r"(a0), "r"(a1), "r"(a2), "r"(a3), "r"(b0), "r"(b1));
}

__device__ __forceinline__ void ldsm_x4(uint32_t* r, uint32_t addr)
{
    asm volatile("ldmatrix.sync.aligned.m8n8.x4.shared.b16 {%0,%1,%2,%3}, [%4];"
                 : "=r"(r[0]), "=r"(r[1]), "=r"(r[2]), "=r"(r[3]) : "r"(addr));
}

__device__ __forceinline__ uint32_t smem_u32(const void* p) {
    uint32_t a;
    asm("{ .reg .u64 t; cvta.to.shared.u64 t, %1; cvt.u32.u64 %0, t; }" : "=r"(a) : "l"(p));
    return a;
}

__device__ __forceinline__ void cp_async16(uint32_t saddr, const void* gaddr)
{
    asm volatile("cp.async.cg.shared.global [%0], [%1], 16;" :: "r"(saddr), "l"(gaddr));
}
#define CP_COMMIT() asm volatile("cp.async.commit_group;" ::: "memory")
#define CP_WAIT(n)  asm volatile("cp.async.wait_group %0;" :: "n"(n) : "memory")

// ---------------------------------------------------------------------------
// Weight conversion fp32 -> fp16
// ---------------------------------------------------------------------------
__global__ void cvt_half_kernel(const float4* __restrict__ src, uint2* __restrict__ dst, size_t n4)
{
    for (size_t i = (size_t)blockIdx.x * blockDim.x + threadIdx.x; i < n4;
         i += (size_t)gridDim.x * blockDim.x) {
        float4 v = src[i];
        __half2 lo = __floats2half2_rn(v.x, v.y);
        __half2 hi = __floats2half2_rn(v.z, v.w);
        dst[i] = make_uint2(*(uint32_t*)&lo, *(uint32_t*)&hi);
    }
}

__global__ void cvt_wih0_kernel(const float* __restrict__ w)
{
    size_t i = (size_t)blockIdx.x * blockDim.x + threadIdx.x;
    if (i >= (size_t)2 * G3 * INWP) return;
    int c = (int)(i % INWP);
    size_t r = i / INWP;
    g_wih0h[i] = __float2half_rn((c < INW) ? w[r * INW + c] : 0.f);
}

// ---------------------------------------------------------------------------
// BatchNorm
// ---------------------------------------------------------------------------
__global__ void bn_stats_kernel(const float* __restrict__ x)
{
    int c = blockIdx.x;
    float s = 0.f, s2 = 0.f;
    for (int i = threadIdx.x; i < NT; i += blockDim.x) {
        float v = x[(size_t)i * INW + c];
        s += v; s2 += v * v;
    }
    __shared__ float sh0[256], sh1[256];
    sh0[threadIdx.x] = s; sh1[threadIdx.x] = s2;
    __syncthreads();
    for (int off = 128; off > 0; off >>= 1) {
        if (threadIdx.x < off) {
            sh0[threadIdx.x] += sh0[threadIdx.x + off];
            sh1[threadIdx.x] += sh1[threadIdx.x + off];
        }
        __syncthreads();
    }
    if (threadIdx.x == 0) {
        float mean = sh0[0] / (float)NT;
        float var  = sh1[0] / (float)NT - mean * mean;
        g_bn[c]       = mean;
        g_bn[INW + c] = rsqrtf(var + 1e-5f);
    }
}

__global__ void bn_apply_kernel(const float* __restrict__ x,
                                const float* __restrict__ gamma,
                                const float* __restrict__ beta)
{
    size_t i = (size_t)blockIdx.x * blockDim.x + threadIdx.x;
    if (i >= (size_t)NT * INWP) return;
    int c = (int)(i % INWP);
    size_t r = i / INWP;
    float v = 0.f;
    if (c < INW)
        v = (x[r * INW + c] - g_bn[c]) * g_bn[INW + c] * gamma[c] + beta[c];
    g_xn[i] = __float2half_rn(v);
}

// ---------------------------------------------------------------------------
// Input GEMM (unchanged from R6): C[M,N] = A[M,K]*B[N,K]^T + bias[N]
// CTA 128x128x32, 8 warps, 4-stage cp.async, ldmatrix.
// ---------------------------------------------------------------------------
#define STAGES 4
#define ROWB   80
#define STAGEB (128 * ROWB)
#define GEMM_SMEM (STAGES * 2 * STAGEB)

__global__ __launch_bounds__(256, 2)
void gemm_f16_pipe(const __half* __restrict__ A, const __half* __restrict__ B,
                   const float* __restrict__ bias, float* __restrict__ C,
                   int M, int N, int K,
                   long sAz, long sBz, long sbz, long sCz)
{
    extern __shared__ __align__(16) char smem[];
    const uint32_t sA0 = smem_u32(smem);
    const uint32_t sB0 = sA0 + STAGES * STAGEB;

    const int bz = blockIdx.z;
    A    += (long)bz * sAz;
    B    += (long)bz * sBz;
    bias += (long)bz * sbz;
    C    += (long)bz * sCz;

    const int n0 = blockIdx.x * 128;
    const int m0 = blockIdx.y * 128;
    const int tid  = threadIdx.x;
    const int warp = tid >> 5;
    const int lane = tid & 31;
    const int wm = warp & 1;
    const int wn = warp >> 1;

    const uint32_t aoff = (uint32_t)(wm * 64 + (lane & 7) + ((lane >> 3) & 1) * 8) * ROWB
                        + ((lane >> 4) & 1) * 16;
    const uint32_t boff = (uint32_t)(wn * 32 + (lane & 7) + ((lane >> 4) & 1) * 8) * ROWB
                        + ((lane >> 3) & 1) * 16;

    const int crow = tid >> 1;
    const int chal = tid & 1;
    const char* Ag = (const char*)(A + (long)(m0 + crow) * K) + chal * 32;
    const char* Bg = (const char*)(B + (long)(n0 + crow) * K) + chal * 32;
    const uint32_t sArow = sA0 + crow * ROWB + chal * 32;
    const uint32_t sBrow = sB0 + crow * ROWB + chal * 32;

    float acc[4][4][4];
    #pragma unroll
    for (int i = 0; i < 4; i++)
        #pragma unroll
        for (int j = 0; j < 4; j++)
            #pragma unroll
            for (int q = 0; q < 4; q++) acc[i][j][q] = 0.f;

    const int KT = K >> 5;

    #pragma unroll
    for (int p = 0; p < STAGES - 1; p++) {
        const char* ag = Ag + p * 64;
        const char* bg = Bg + p * 64;
        const uint32_t sa = sArow + p * STAGEB;
        const uint32_t sb = sBrow + p * STAGEB;
        cp_async16(sa, ag);  cp_async16(sa + 16, ag + 16);
        cp_async16(sb, bg);  cp_async16(sb + 16, bg + 16);
        CP_COMMIT();
    }

    for (int kt = 0; kt < KT; kt++) {
        if      (kt <= KT - 3) { CP_WAIT(2); }
        else if (kt == KT - 2) { CP_WAIT(1); }
        else                   { CP_WAIT(0); }
        __syncthreads();

        if (kt + STAGES - 1 < KT) {
            const int nt = kt + STAGES - 1;
            const int sb_ = nt & 3;
            const char* ag = Ag + nt * 64;
            const char* bg = Bg + nt * 64;
            const uint32_t sa = sArow + sb_ * STAGEB;
            const uint32_t sbm = sBrow + sb_ * STAGEB;
            cp_async16(sa, ag);   cp_async16(sa + 16, ag + 16);
            cp_async16(sbm, bg);  cp_async16(sbm + 16, bg + 16);
            CP_COMMIT();
        }

        const int buf = kt & 3;
        const uint32_t aBase = sA0 + buf * STAGEB + aoff;
        const uint32_t bBase = sB0 + buf * STAGEB + boff;

        #pragma unroll
        for (int s = 0; s < 2; s++) {
            uint32_t a[4][4], b[2][4];
            #pragma unroll
            for (int i = 0; i < 4; i++)
                ldsm_x4(a[i], aBase + i * 16 * ROWB + s * 32);
            #pragma unroll
            for (int j2 = 0; j2 < 2; j2++)
                ldsm_x4(b[j2], bBase + j2 * 16 * ROWB + s * 32);

            #pragma unroll
            for (int i = 0; i < 4; i++)
                #pragma unroll
                for (int j2 = 0; j2 < 2; j2++) {
                    mma_f16(acc[i][2 * j2],     a[i][0], a[i][1], a[i][2], a[i][3],
                            b[j2][0], b[j2][1]);
                    mma_f16(acc[i][2 * j2 + 1], a[i][0], a[i][1], a[i][2], a[i][3],
                            b[j2][2], b[j2][3]);
                }
        }
        __syncthreads();
    }

    #pragma unroll
    for (int i = 0; i < 4; i++) {
        const int row = m0 + wm * 64 + i * 16 + (lane >> 2);
        #pragma unroll
        for (int j = 0; j < 4; j++) {
            const int col = n0 + wn * 32 + j * 8 + (lane & 3) * 2;
            const float bx = __ldg(&bias[col]);
            const float by = __ldg(&bias[col + 1]);
            *(float2*)&C[(long)row * N + col] =
                make_float2(acc[i][j][0] + bx, acc[i][j][1] + by);
            *(float2*)&C[(long)(row + 8) * N + col] =
                make_float2(acc[i][j][2] + bx, acc[i][j][3] + by);
        }
    }
}

// ---------------------------------------------------------------------------
// Fused recurrent step:  gh = h_d @ W_hh^T (+b_hh) followed by GRU gate math,
// state update, and output store — one kernel per timestep.
// CTA: 64 batch rows x 192 gate-cols (= {r,z,n} x 64 units), K = 1024.
// Grid: (HH/64 = 16, NB/64 = 4, 2 dirs) = 128 CTAs, 256 threads.
// 4-stage cp.async pipeline, ldmatrix, warp tile 32x48.
// ---------------------------------------------------------------------------
#define R_AROWS 64
#define R_BROWS 192
#define R_ASTG  (R_AROWS * ROWB)              // 5120
#define R_BSTG  (R_BROWS * ROWB)              // 15360
#define R_STG   (R_ASTG + R_BSTG)             // 20480
#define R_SMEM  (STAGES * R_STG)              // 81920
#define R_KT    (HH / 32)                     // 32
#define GH_PITCH 196                          // floats, padded

__global__ __launch_bounds__(256, 1)
void gru_step_fused(const __half* __restrict__ Wh,    // [2][G3][HH] for this layer
                    const float* __restrict__ bhh,    // [2][G3]
                    __half* __restrict__ out_h, float* __restrict__ out_f,
                    int t)
{
    extern __shared__ __align__(16) char smem[];
    const uint32_t s0 = smem_u32(smem);

    const int d  = blockIdx.z;
    const int u0 = blockIdx.x * 64;     // unit block
    const int m0 = blockIdx.y * 64;     // batch block
    const int tid  = threadIdx.x;
    const int warp = tid >> 5;
    const int lane = tid & 31;
    const int wm = warp & 1;            // 2 M-halves of 32
    const int wn = warp >> 1;           // 4 N-quarters of 48

    const __half* A  = g_hh[d];                         // [NB][HH]
    const __half* Bd = Wh + (size_t)d * G3 * HH;
    const float*  bb = bhh + (size_t)d * G3;

    // --- cp.async: thread owns one full row (64B per k32 tile) ---
    const char* grow_ptr;
    uint32_t    srow_off;
    if (tid < R_AROWS) {
        grow_ptr = (const char*)(A + (long)(m0 + tid) * HH);
        srow_off = tid * ROWB;
    } else {
        const int br   = tid - R_AROWS;       // 0..191
        const int gate = br >> 6;
        const int ur   = br & 63;
        grow_ptr = (const char*)(Bd + (long)(gate * HH + u0 + ur) * HH);
        srow_off = R_ASTG + br * ROWB;
    }

    // ldmatrix per-lane offsets
    const uint32_t aoff = (uint32_t)(wm * 32 + (lane & 7) + ((lane >> 3) & 1) * 8) * ROWB
                        + ((lane >> 4) & 1) * 16;
    const uint32_t boff = R_ASTG
                        + (uint32_t)(wn * 48 + (lane & 7) + ((lane >> 4) & 1) * 8) * ROWB
                        + ((lane >> 3) & 1) * 16;

    float acc[2][6][4];
    #pragma unroll
    for (int i = 0; i < 2; i++)
        #pragma unroll
        for (int j = 0; j < 6; j++)
            #pragma unroll
            for (int q = 0; q < 4; q++) acc[i][j][q] = 0.f;

    // prologue
    #pragma unroll
    for (int p = 0; p < STAGES - 1; p++) {
        const char* gp = grow_ptr + p * 64;
        const uint32_t sa = s0 + p * R_STG + srow_off;
        cp_async16(sa,      gp);
        cp_async16(sa + 16, gp + 16);
        cp_async16(sa + 32, gp + 32);
        cp_async16(sa + 48, gp + 48);
        CP_COMMIT();
    }

    for (int kt = 0; kt < R_KT; kt++) {
        if      (kt <= R_KT - 3) { CP_WAIT(2); }
        else if (kt == R_KT - 2) { CP_WAIT(1); }
        else                     { CP_WAIT(0); }
        __syncthreads();

        if (kt + STAGES - 1 < R_KT) {
            const int nt = kt + STAGES - 1;
            const char* gp = grow_ptr + nt * 64;
            const uint32_t sa = s0 + (nt & 3) * R_STG + srow_off;
            cp_async16(sa,      gp);
            cp_async16(sa + 16, gp + 16);
            cp_async16(sa + 32, gp + 32);
            cp_async16(sa + 48, gp + 48);
            CP_COMMIT();
        }

        const int buf = kt & 3;
        const uint32_t aBase = s0 + buf * R_STG + aoff;
        const uint32_t bBase = s0 + buf * R_STG + boff;

        #pragma unroll
        for (int s = 0; s < 2; s++) {
            uint32_t a[2][4], b[3][4];
            #pragma unroll
            for (int i = 0; i < 2; i++)
                ldsm_x4(a[i], aBase + i * 16 * ROWB + s * 32);
            #pragma unroll
            for (int j2 = 0; j2 < 3; j2++)
                ldsm_x4(b[j2], bBase + j2 * 16 * ROWB + s * 32);

            #pragma unroll
            for (int i = 0; i < 2; i++)
                #pragma unroll
                for (int j2 = 0; j2 < 3; j2++) {
                    mma_f16(acc[i][2 * j2],     a[i][0], a[i][1], a[i][2], a[i][3],
                            b[j2][0], b[j2][1]);
                    mma_f16(acc[i][2 * j2 + 1], a[i][0], a[i][1], a[i][2], a[i][3],
                            b[j2][2], b[j2][3]);
                }
        }
        __syncthreads();
    }

    // --- stage gh to smem (reuse pipeline buffers) ---
    float* ghs = (float*)smem;
    #pragma unroll
    for (int i = 0; i < 2; i++) {
        const int row = wm * 32 + i * 16 + (lane >> 2);
        #pragma unroll
        for (int j = 0; j < 6; j++) {
            const int col = wn * 48 + j * 8 + (lane & 3) * 2;
            *(float2*)&ghs[row * GH_PITCH + col] =
                make_float2(acc[i][j][0], acc[i][j][1]);
            *(float2*)&ghs[(row + 8) * GH_PITCH + col] =
                make_float2(acc[i][j][2], acc[i][j][3]);
        }
    }
    __syncthreads();

    // --- gate math: 64 rows x 64 units = 4096 elems, 16 per thread ---
    #pragma unroll
    for (int e = 0; e < 16; e++) {
        const int idx = tid + e * 256;
        const int row = idx >> 6;
        const int u   = idx & 63;
        const int nrow = m0 + row;
        const int unit = u0 + u;

        const float hr = ghs[row * GH_PITCH + u]        + __ldg(&bb[unit]);
        const float hz = ghs[row * GH_PITCH + 64 + u]   + __ldg(&bb[HH + unit]);
        const float hn = ghs[row * GH_PITCH + 128 + u]  + __ldg(&bb[2 * HH + unit]);

        const float* gib = g_gi[d] + ((size_t)(nrow * TT + t)) * G3 + unit;
        const float ir = gib[0], iz = gib[HH], inn = gib[2 * HH];

        const float r  = 1.f / (1.f + __expf(-(ir + hr)));
        const float z  = 1.f / (1.f + __expf(-(iz + hz)));
        const float nn = tanhf(inn + r * hn);

        float* hp = &g_h[d][(size_t)nrow * HH + unit];
        const float hnew = (1.f - z) * nn + z * (*hp);
        *hp = hnew;
        g_hh[d][(size_t)nrow * HH + unit] = __float2half_rn(hnew);

        const size_t ob = (size_t)(nrow * TT + t) * H2 + (size_t)d * HH + unit;
        if (out_f) out_f[ob] = hnew;
        else       out_h[ob] = __float2half_rn(hnew);
    }
}

// ---------------------------------------------------------------------------
// hidden state zero
// ---------------------------------------------------------------------------
__global__ void hzero_kernel()
{
    size_t i = (size_t)blockIdx.x * blockDim.x + threadIdx.x;
    if (i < (size_t)2 * NB * HH) {
        ((float*)g_h)[i] = 0.f;
        ((__half*)g_hh)[i] = __float2half_rn(0.f);
    }
}

// ---------------------------------------------------------------------------
// FC head
// ---------------------------------------------------------------------------
__global__ void fc_kernel(const float* __restrict__ enc,
                          const float* __restrict__ fc_w,
                          const float* __restrict__ fc_b,
                          float* __restrict__ out)
{
    int n = blockIdx.x;
    int c = threadIdx.x;
    if (c >= NCLS) return;
    const float* h = enc + ((size_t)n * TT + (TT - 1)) * H2;
    const float* w = fc_w + (size_t)c * H2;
    float s = 0.f;
    #pragma unroll 8
    for (int k = 0; k < H2; k++) s += h[k] * w[k];
    out[n * NCLS + c] = s + fc_b[c];
}

// ---------------------------------------------------------------------------
// Orchestration
// ---------------------------------------------------------------------------
extern "C" void kernel_launch(void* const* d_in, const int* in_sizes, int n_in,
                              void* d_out, int out_size)
{
    const float* x        = (const float*)d_in[0];
    const float* bn_gamma = (const float*)d_in[1];
    const float* bn_beta  = (const float*)d_in[2];
    const float* w_ih[3]  = {(const float*)d_in[3],  (const float*)d_in[7],  (const float*)d_in[11]};
    const float* w_hh[3]  = {(const float*)d_in[4],  (const float*)d_in[8],  (const float*)d_in[12]};
    const float* b_ih[3]  = {(const float*)d_in[5],  (const float*)d_in[9],  (const float*)d_in[13]};
    const float* b_hh[3]  = {(const float*)d_in[6],  (const float*)d_in[10], (const float*)d_in[14]};
    const float* fc_w     = (const float*)d_in[15];
    const float* fc_b     = (const float*)d_in[16];

    float* out = (float*)d_out;
    float* enc = out + (size_t)NB * NCLS;

    __half *p_xn, *p_wih0h, *p_wih1h, *p_wih2h, *p_whhh, *p_bufAh, *p_bufBh;
    float  *p_gi;
    cudaGetSymbolAddress((void**)&p_xn,    g_xn);
    cudaGetSymbolAddress((void**)&p_wih0h, g_wih0h);
    cudaGetSymbolAddress((void**)&p_wih1h, g_wih1h);
    cudaGetSymbolAddress((void**)&p_wih2h, g_wih2h);
    cudaGetSymbolAddress((void**)&p_whhh,  g_whhh);
    cudaGetSymbolAddress((void**)&p_gi,    g_gi);
    cudaGetSymbolAddress((void**)&p_bufAh, g_bufAh);
    cudaGetSymbolAddress((void**)&p_bufBh, g_bufBh);

    cudaFuncSetAttribute(gemm_f16_pipe,  cudaFuncAttributeMaxDynamicSharedMemorySize, GEMM_SMEM);
    cudaFuncSetAttribute(gru_step_fused, cudaFuncAttributeMaxDynamicSharedMemorySize, R_SMEM);

    // ---- weight conversions ----
    {
        size_t n0 = (size_t)2 * G3 * INWP;
        cvt_wih0_kernel<<<(unsigned)((n0 + 255) / 256), 256>>>(w_ih[0]);
        size_t n1 = (size_t)2 * G3 * H2;
        cvt_half_kernel<<<1024, 256>>>((const float4*)w_ih[1], (uint2*)p_wih1h, n1 / 4);
        cvt_half_kernel<<<1024, 256>>>((const float4*)w_ih[2], (uint2*)p_wih2h, n1 / 4);
        size_t nh = (size_t)2 * G3 * HH;
        cvt_half_kernel<<<1024, 256>>>((const float4*)w_hh[0], (uint2*)(p_whhh + 0 * nh), nh / 4);
        cvt_half_kernel<<<1024, 256>>>((const float4*)w_hh[1], (uint2*)(p_whhh + 1 * nh), nh / 4);
        cvt_half_kernel<<<1024, 256>>>((const float4*)w_hh[2], (uint2*)(p_whhh + 2 * nh), nh / 4);
    }

    // ---- BatchNorm ----
    bn_stats_kernel<<<INW, 256>>>(x);
    {
        size_t n = (size_t)NT * INWP;
        bn_apply_kernel<<<(unsigned)((n + 255) / 256), 256>>>(x, bn_gamma, bn_beta);
    }

    const __half* layer_in[3]   = {p_xn, p_bufAh, p_bufBh};
    __half*       layer_outh[3] = {p_bufAh, p_bufBh, nullptr};
    float*        layer_outf[3] = {nullptr, nullptr, enc};
    const int     layer_k[3]    = {INWP, H2, H2};
    const __half* layer_wih[3]  = {p_wih0h, p_wih1h, p_wih2h};
    const size_t  nh = (size_t)2 * G3 * HH;

    for (int l = 0; l < 3; l++) {
        const int K = layer_k[l];

        // gi[d] = X @ w_ih[l][d]^T + b_ih[l][d]
        {
            dim3 grid(G3 / 128, NT / 128, 2);
            gemm_f16_pipe<<<grid, 256, GEMM_SMEM>>>(layer_in[l], layer_wih[l], b_ih[l], p_gi,
                                                    NT, G3, K,
                                                    0L, (long)G3 * K, (long)G3, (long)NT * G3);
        }

        hzero_kernel<<<(2 * NB * HH) / 256, 256>>>();

        // fused recurrent steps
        {
            dim3 grid(HH / 64, NB / 64, 2);
            for (int t = 0; t < TT; t++) {
                gru_step_fused<<<grid, 256, R_SMEM>>>(p_whhh + (size_t)l * nh, b_hh[l],
                                                      layer_outh[l], layer_outf[l], t);
            }
        }
    }

    fc_kernel<<<NB, 64>>>(enc, fc_w, fc_b, out);
}

// round 8
// speedup vs baseline: 1.2732x; 1.2732x over previous
#include <cuda_runtime.h>
#include <cuda_fp16.h>
#include <cstdint>
#include <math.h>

// ---------------------------------------------------------------------------
// Problem constants
// ---------------------------------------------------------------------------
#define NB   256
#define TT   64
#define INW  150
#define INWP 160
#define HH   1024
#define G3   (3*HH)
#define H2   (2*HH)
#define NT   (NB*TT)
#define NCLS 60

// ---------------------------------------------------------------------------
// Device scratch
// ---------------------------------------------------------------------------
__device__ __half g_xn   [(size_t)NT * INWP];
__device__ __half g_wih0h[(size_t)2 * G3 * INWP];
__device__ __half g_wih1h[(size_t)2 * G3 * H2];
__device__ __half g_wih2h[(size_t)2 * G3 * H2];
__device__ __half g_whhh [3][(size_t)2 * G3 * HH];
__device__ float  g_gi   [2][(size_t)NT * G3];
__device__ __half g_bufAh[(size_t)NT * H2];
__device__ __half g_bufBh[(size_t)NT * H2];
__device__ float  g_h    [2][(size_t)NB * HH];
__device__ __half g_hh   [2][(size_t)NB * HH];
__device__ float  g_gh   [2][(size_t)NB * G3];
__device__ float  g_bn   [2 * INW];

// ---------------------------------------------------------------------------
// PTX helpers
// ---------------------------------------------------------------------------
__device__ __forceinline__ void mma_f16(float* d,
                                        uint32_t a0, uint32_t a1, uint32_t a2, uint32_t a3,
                                        uint32_t b0, uint32_t b1)
{
    asm volatile(
        "mma.sync.aligned.m16n8k16.row.col.f32.f16.f16.f32 "
        "{%0,%1,%2,%3}, {%4,%5,%6,%7}, {%8,%9}, {%0,%1,%2,%3};"
        : "+f"(d[0]), "+f"(d[1]), "+f"(d[2]), "+f"(d[3])
        : "r"(a0), "r"(a1), "r"(a2), "r"(a3), "r"(b0), "r"(b1));
}

__device__ __forceinline__ void ldsm_x4(uint32_t* r, uint32_t addr)
{
    asm volatile("ldmatrix.sync.aligned.m8n8.x4.shared.b16 {%0,%1,%2,%3}, [%4];"
                 : "=r"(r[0]), "=r"(r[1]), "=r"(r[2]), "=r"(r[3]) : "r"(addr));
}

__device__ __forceinline__ uint32_t smem_u32(const void* p) {
    uint32_t a;
    asm("{ .reg .u64 t; cvta.to.shared.u64 t, %1; cvt.u32.u64 %0, t; }" : "=r"(a) : "l"(p));
    return a;
}

__device__ __forceinline__ void cp_async16(uint32_t saddr, const void* gaddr)
{
    asm volatile("cp.async.cg.shared.global [%0], [%1], 16;" :: "r"(saddr), "l"(gaddr));
}
#define CP_COMMIT() asm volatile("cp.async.commit_group;" ::: "memory")
#define CP_WAIT(n)  asm volatile("cp.async.wait_group %0;" :: "n"(n) : "memory")

// ---------------------------------------------------------------------------
// Weight conversion fp32 -> fp16
// ---------------------------------------------------------------------------
__global__ void cvt_half_kernel(const float4* __restrict__ src, uint2* __restrict__ dst, size_t n4)
{
    for (size_t i = (size_t)blockIdx.x * blockDim.x + threadIdx.x; i < n4;
         i += (size_t)gridDim.x * blockDim.x) {
        float4 v = src[i];
        __half2 lo = __floats2half2_rn(v.x, v.y);
        __half2 hi = __floats2half2_rn(v.z, v.w);
        dst[i] = make_uint2(*(uint32_t*)&lo, *(uint32_t*)&hi);
    }
}

__global__ void cvt_wih0_kernel(const float* __restrict__ w)
{
    size_t i = (size_t)blockIdx.x * blockDim.x + threadIdx.x;
    if (i >= (size_t)2 * G3 * INWP) return;
    int c = (int)(i % INWP);
    size_t r = i / INWP;
    g_wih0h[i] = __float2half_rn((c < INW) ? w[r * INW + c] : 0.f);
}

// ---------------------------------------------------------------------------
// BatchNorm
// ---------------------------------------------------------------------------
__global__ void bn_stats_kernel(const float* __restrict__ x)
{
    int c = blockIdx.x;
    float s = 0.f, s2 = 0.f;
    for (int i = threadIdx.x; i < NT; i += blockDim.x) {
        float v = x[(size_t)i * INW + c];
        s += v; s2 += v * v;
    }
    __shared__ float sh0[256], sh1[256];
    sh0[threadIdx.x] = s; sh1[threadIdx.x] = s2;
    __syncthreads();
    for (int off = 128; off > 0; off >>= 1) {
        if (threadIdx.x < off) {
            sh0[threadIdx.x] += sh0[threadIdx.x + off];
            sh1[threadIdx.x] += sh1[threadIdx.x + off];
        }
        __syncthreads();
    }
    if (threadIdx.x == 0) {
        float mean = sh0[0] / (float)NT;
        float var  = sh1[0] / (float)NT - mean * mean;
        g_bn[c]       = mean;
        g_bn[INW + c] = rsqrtf(var + 1e-5f);
    }
}

__global__ void bn_apply_kernel(const float* __restrict__ x,
                                const float* __restrict__ gamma,
                                const float* __restrict__ beta)
{
    size_t i = (size_t)blockIdx.x * blockDim.x + threadIdx.x;
    if (i >= (size_t)NT * INWP) return;
    int c = (int)(i % INWP);
    size_t r = i / INWP;
    float v = 0.f;
    if (c < INW)
        v = (x[r * INW + c] - g_bn[c]) * g_bn[INW + c] * gamma[c] + beta[c];
    g_xn[i] = __float2half_rn(v);
}

// ---------------------------------------------------------------------------
// BIG input GEMM:  C[M,N] = A[M,K]*B[N,K]^T + bias[N]
// CTA 128x256x32, 8 warps (2M x 4N), warp tile 64x64 (4x8 m16n8k16).
// 3-stage cp.async pipeline, ldmatrix.x4, 80B row stride.
// Requires M % 128 == 0, N % 256 == 0, K % 32 == 0, K/32 >= 2.
// ---------------------------------------------------------------------------
#define ROWB    80
#define BSTAGES 3
#define B_ROWS  (128 + 256)                    // A rows + B rows
#define B_STG   (B_ROWS * ROWB)                // 30720
#define BGEMM_SMEM (BSTAGES * B_STG)           // 92160

__global__ __launch_bounds__(256, 1)
void gemm_f16_big(const __half* __restrict__ A, const __half* __restrict__ B,
                  const float* __restrict__ bias, float* __restrict__ C,
                  int M, int N, int K,
                  long sAz, long sBz, long sbz, long sCz)
{
    extern __shared__ __align__(16) char smem[];
    const uint32_t s0 = smem_u32(smem);

    const int bz = blockIdx.z;
    A    += (long)bz * sAz;
    B    += (long)bz * sBz;
    bias += (long)bz * sbz;
    C    += (long)bz * sCz;

    const int n0 = blockIdx.x * 256;
    const int m0 = blockIdx.y * 128;
    const int tid  = threadIdx.x;
    const int warp = tid >> 5;
    const int lane = tid & 31;
    const int wm = warp & 1;      // 2 M-halves of 64
    const int wn = warp >> 1;     // 4 N-quarters of 64

    // ldmatrix per-lane offsets
    const uint32_t aoff = (uint32_t)(wm * 64 + (lane & 7) + ((lane >> 3) & 1) * 8) * ROWB
                        + ((lane >> 4) & 1) * 16;
    const uint32_t boff = (uint32_t)(128 + wn * 64 + (lane & 7) + ((lane >> 4) & 1) * 8) * ROWB
                        + ((lane >> 3) & 1) * 16;

    // cp.async mapping: 384 rows x 4 chunks(16B) = 1536 chunks; 6 per thread
    const char* gptr[6];
    uint32_t    soff[6];
    #pragma unroll
    for (int c = 0; c < 6; c++) {
        const int chunk = c * 256 + tid;
        const int row  = chunk >> 2;
        const int part = chunk & 3;
        if (row < 128) {
            gptr[c] = (const char*)(A + (long)(m0 + row) * K) + part * 16;
            soff[c] = (uint32_t)row * ROWB + part * 16;
        } else {
            gptr[c] = (const char*)(B + (long)(n0 + row - 128) * K) + part * 16;
            soff[c] = (uint32_t)row * ROWB + part * 16;   // rows 128.. map after A region
        }
    }

    float acc[4][8][4];
    #pragma unroll
    for (int i = 0; i < 4; i++)
        #pragma unroll
        for (int j = 0; j < 8; j++)
            #pragma unroll
            for (int q = 0; q < 4; q++) acc[i][j][q] = 0.f;

    const int KT = K >> 5;

    // prologue: issue tiles 0,1
    #pragma unroll
    for (int p = 0; p < BSTAGES - 1; p++) {
        #pragma unroll
        for (int c = 0; c < 6; c++)
            cp_async16(s0 + p * B_STG + soff[c], gptr[c] + p * 64);
        CP_COMMIT();
    }

    for (int kt = 0; kt < KT; kt++) {
        if (kt < KT - 1) { CP_WAIT(1); } else { CP_WAIT(0); }
        __syncthreads();

        if (kt + BSTAGES - 1 < KT) {
            const int nt = kt + BSTAGES - 1;
            const uint32_t sbase = s0 + (nt % BSTAGES) * B_STG;
            #pragma unroll
            for (int c = 0; c < 6; c++)
                cp_async16(sbase + soff[c], gptr[c] + nt * 64);
            CP_COMMIT();
        }

        const uint32_t stg = s0 + (kt % BSTAGES) * B_STG;
        const uint32_t aBase = stg + aoff;
        const uint32_t bBase = stg + boff;

        #pragma unroll
        for (int s = 0; s < 2; s++) {
            uint32_t a[4][4], b[4][4];
            #pragma unroll
            for (int i = 0; i < 4; i++)
                ldsm_x4(a[i], aBase + i * 16 * ROWB + s * 32);
            #pragma unroll
            for (int j2 = 0; j2 < 4; j2++)
                ldsm_x4(b[j2], bBase + j2 * 16 * ROWB + s * 32);

            #pragma unroll
            for (int i = 0; i < 4; i++)
                #pragma unroll
                for (int j2 = 0; j2 < 4; j2++) {
                    mma_f16(acc[i][2 * j2],     a[i][0], a[i][1], a[i][2], a[i][3],
                            b[j2][0], b[j2][1]);
                    mma_f16(acc[i][2 * j2 + 1], a[i][0], a[i][1], a[i][2], a[i][3],
                            b[j2][2], b[j2][3]);
                }
        }
        __syncthreads();
    }

    // epilogue
    #pragma unroll
    for (int i = 0; i < 4; i++) {
        const int row = m0 + wm * 64 + i * 16 + (lane >> 2);
        #pragma unroll
        for (int j = 0; j < 8; j++) {
            const int col = n0 + wn * 64 + j * 8 + (lane & 3) * 2;
            const float bx = __ldg(&bias[col]);
            const float by = __ldg(&bias[col + 1]);
            *(float2*)&C[(long)row * N + col] =
                make_float2(acc[i][j][0] + bx, acc[i][j][1] + by);
            *(float2*)&C[(long)(row + 8) * N + col] =
                make_float2(acc[i][j][2] + bx, acc[i][j][3] + by);
        }
    }
}

// ---------------------------------------------------------------------------
// Recurrent GEMM (proven R6 config): CTA 128x128x32, 8 warps, warp 64x32,
// 4-stage cp.async, ldmatrix.
// ---------------------------------------------------------------------------
#define STAGES 4
#define STAGEB (128 * ROWB)
#define GEMM_SMEM (STAGES * 2 * STAGEB)

__global__ __launch_bounds__(256, 2)
void gemm_f16_pipe(const __half* __restrict__ A, const __half* __restrict__ B,
                   const float* __restrict__ bias, float* __restrict__ C,
                   int M, int N, int K,
                   long sAz, long sBz, long sbz, long sCz)
{
    extern __shared__ __align__(16) char smem[];
    const uint32_t sA0 = smem_u32(smem);
    const uint32_t sB0 = sA0 + STAGES * STAGEB;

    const int bz = blockIdx.z;
    A    += (long)bz * sAz;
    B    += (long)bz * sBz;
    bias += (long)bz * sbz;
    C    += (long)bz * sCz;

    const int n0 = blockIdx.x * 128;
    const int m0 = blockIdx.y * 128;
    const int tid  = threadIdx.x;
    const int warp = tid >> 5;
    const int lane = tid & 31;
    const int wm = warp & 1;
    const int wn = warp >> 1;

    const uint32_t aoff = (uint32_t)(wm * 64 + (lane & 7) + ((lane >> 3) & 1) * 8) * ROWB
                        + ((lane >> 4) & 1) * 16;
    const uint32_t boff = (uint32_t)(wn * 32 + (lane & 7) + ((lane >> 4) & 1) * 8) * ROWB
                        + ((lane >> 3) & 1) * 16;

    const int crow = tid >> 1;
    const int chal = tid & 1;
    const char* Ag = (const char*)(A + (long)(m0 + crow) * K) + chal * 32;
    const char* Bg = (const char*)(B + (long)(n0 + crow) * K) + chal * 32;
    const uint32_t sArow = sA0 + crow * ROWB + chal * 32;
    const uint32_t sBrow = sB0 + crow * ROWB + chal * 32;

    float acc[4][4][4];
    #pragma unroll
    for (int i = 0; i < 4; i++)
        #pragma unroll
        for (int j = 0; j < 4; j++)
            #pragma unroll
            for (int q = 0; q < 4; q++) acc[i][j][q] = 0.f;

    const int KT = K >> 5;

    #pragma unroll
    for (int p = 0; p < STAGES - 1; p++) {
        const char* ag = Ag + p * 64;
        const char* bg = Bg + p * 64;
        const uint32_t sa = sArow + p * STAGEB;
        const uint32_t sb = sBrow + p * STAGEB;
        cp_async16(sa, ag);  cp_async16(sa + 16, ag + 16);
        cp_async16(sb, bg);  cp_async16(sb + 16, bg + 16);
        CP_COMMIT();
    }

    for (int kt = 0; kt < KT; kt++) {
        if      (kt <= KT - 3) { CP_WAIT(2); }
        else if (kt == KT - 2) { CP_WAIT(1); }
        else                   { CP_WAIT(0); }
        __syncthreads();

        if (kt + STAGES - 1 < KT) {
            const int nt = kt + STAGES - 1;
            const int sb_ = nt & 3;
            const char* ag = Ag + nt * 64;
            const char* bg = Bg + nt * 64;
            const uint32_t sa = sArow + sb_ * STAGEB;
            const uint32_t sbm = sBrow + sb_ * STAGEB;
            cp_async16(sa, ag);   cp_async16(sa + 16, ag + 16);
            cp_async16(sbm, bg);  cp_async16(sbm + 16, bg + 16);
            CP_COMMIT();
        }

        const int buf = kt & 3;
        const uint32_t aBase = sA0 + buf * STAGEB + aoff;
        const uint32_t bBase = sB0 + buf * STAGEB + boff;

        #pragma unroll
        for (int s = 0; s < 2; s++) {
            uint32_t a[4][4], b[2][4];
            #pragma unroll
            for (int i = 0; i < 4; i++)
                ldsm_x4(a[i], aBase + i * 16 * ROWB + s * 32);
            #pragma unroll
            for (int j2 = 0; j2 < 2; j2++)
                ldsm_x4(b[j2], bBase + j2 * 16 * ROWB + s * 32);

            #pragma unroll
            for (int i = 0; i < 4; i++)
                #pragma unroll
                for (int j2 = 0; j2 < 2; j2++) {
                    mma_f16(acc[i][2 * j2],     a[i][0], a[i][1], a[i][2], a[i][3],
                            b[j2][0], b[j2][1]);
                    mma_f16(acc[i][2 * j2 + 1], a[i][0], a[i][1], a[i][2], a[i][3],
                            b[j2][2], b[j2][3]);
                }
        }
        __syncthreads();
    }

    #pragma unroll
    for (int i = 0; i < 4; i++) {
        const int row = m0 + wm * 64 + i * 16 + (lane >> 2);
        #pragma unroll
        for (int j = 0; j < 4; j++) {
            const int col = n0 + wn * 32 + j * 8 + (lane & 3) * 2;
            const float bx = __ldg(&bias[col]);
            const float by = __ldg(&bias[col + 1]);
            *(float2*)&C[(long)row * N + col] =
                make_float2(acc[i][j][0] + bx, acc[i][j][1] + by);
            *(float2*)&C[(long)(row + 8) * N + col] =
                make_float2(acc[i][j][2] + bx, acc[i][j][3] + by);
        }
    }
}

// ---------------------------------------------------------------------------
// hidden state zero
// ---------------------------------------------------------------------------
__global__ void hzero_kernel()
{
    size_t i = (size_t)blockIdx.x * blockDim.x + threadIdx.x;
    if (i < (size_t)2 * NB * HH) {
        ((float*)g_h)[i] = 0.f;
        ((__half*)g_hh)[i] = __float2half_rn(0.f);
    }
}

// ---------------------------------------------------------------------------
// GRU gate elementwise
// ---------------------------------------------------------------------------
__global__ void gru_gate_kernel(__half* __restrict__ out_h, float* __restrict__ out_f, int t)
{
    int idx = blockIdx.x * blockDim.x + threadIdx.x;
    if (idx >= 2 * NB * HH / 4) return;
    int d   = idx >> 16;
    int rem = idx & 65535;
    int n   = rem >> 8;
    int jq  = rem & 255;

    const float4* gi = (const float4*)(g_gi[d] + (size_t)(n * TT + t) * G3);
    const float4* gh = (const float4*)(g_gh[d] + (size_t)n * G3);

    float4 ir = gi[jq],       hr = gh[jq];
    float4 iz = gi[256 + jq], hz = gh[256 + jq];
    float4 in = gi[512 + jq], hn = gh[512 + jq];

    float4* hp = (float4*)(g_h[d] + (size_t)n * HH) + jq;
    float4 ho = *hp;
    float4 hv;

    {
        float r = 1.f / (1.f + __expf(-(ir.x + hr.x)));
        float z = 1.f / (1.f + __expf(-(iz.x + hz.x)));
        float nn = tanhf(in.x + r * hn.x);
        hv.x = (1.f - z) * nn + z * ho.x;
    }
    {
        float r = 1.f / (1.f + __expf(-(ir.y + hr.y)));
        float z = 1.f / (1.f + __expf(-(iz.y + hz.y)));
        float nn = tanhf(in.y + r * hn.y);
        hv.y = (1.f - z) * nn + z * ho.y;
    }
    {
        float r = 1.f / (1.f + __expf(-(ir.z + hr.z)));
        float z = 1.f / (1.f + __expf(-(iz.z + hz.z)));
        float nn = tanhf(in.z + r * hn.z);
        hv.z = (1.f - z) * nn + z * ho.z;
    }
    {
        float r = 1.f / (1.f + __expf(-(ir.w + hr.w)));
        float z = 1.f / (1.f + __expf(-(iz.w + hz.w)));
        float nn = tanhf(in.w + r * hn.w);
        hv.w = (1.f - z) * nn + z * ho.w;
    }

    *hp = hv;

    __half2 h01 = __floats2half2_rn(hv.x, hv.y);
    __half2 h23 = __floats2half2_rn(hv.z, hv.w);
    __half2* hhp = (__half2*)(g_hh[d] + (size_t)n * HH + 4 * jq);
    hhp[0] = h01; hhp[1] = h23;

    size_t ob = (size_t)(n * TT + t) * H2 + (size_t)d * HH + 4 * jq;
    if (out_f) {
        *(float4*)(out_f + ob) = hv;
    } else {
        __half2* op = (__half2*)(out_h + ob);
        op[0] = h01; op[1] = h23;
    }
}

// ---------------------------------------------------------------------------
// FC head
// ---------------------------------------------------------------------------
__global__ void fc_kernel(const float* __restrict__ enc,
                          const float* __restrict__ fc_w,
                          const float* __restrict__ fc_b,
                          float* __restrict__ out)
{
    int n = blockIdx.x;
    int c = threadIdx.x;
    if (c >= NCLS) return;
    const float* h = enc + ((size_t)n * TT + (TT - 1)) * H2;
    const float* w = fc_w + (size_t)c * H2;
    float s = 0.f;
    #pragma unroll 8
    for (int k = 0; k < H2; k++) s += h[k] * w[k];
    out[n * NCLS + c] = s + fc_b[c];
}

// ---------------------------------------------------------------------------
// Orchestration
// ---------------------------------------------------------------------------
extern "C" void kernel_launch(void* const* d_in, const int* in_sizes, int n_in,
                              void* d_out, int out_size)
{
    const float* x        = (const float*)d_in[0];
    const float* bn_gamma = (const float*)d_in[1];
    const float* bn_beta  = (const float*)d_in[2];
    const float* w_ih[3]  = {(const float*)d_in[3],  (const float*)d_in[7],  (const float*)d_in[11]};
    const float* w_hh[3]  = {(const float*)d_in[4],  (const float*)d_in[8],  (const float*)d_in[12]};
    const float* b_ih[3]  = {(const float*)d_in[5],  (const float*)d_in[9],  (const float*)d_in[13]};
    const float* b_hh[3]  = {(const float*)d_in[6],  (const float*)d_in[10], (const float*)d_in[14]};
    const float* fc_w     = (const float*)d_in[15];
    const float* fc_b     = (const float*)d_in[16];

    float* out = (float*)d_out;
    float* enc = out + (size_t)NB * NCLS;

    __half *p_xn, *p_wih0h, *p_wih1h, *p_wih2h, *p_whhh, *p_bufAh, *p_bufBh, *p_hh;
    float  *p_gi, *p_gh;
    cudaGetSymbolAddress((void**)&p_xn,    g_xn);
    cudaGetSymbolAddress((void**)&p_wih0h, g_wih0h);
    cudaGetSymbolAddress((void**)&p_wih1h, g_wih1h);
    cudaGetSymbolAddress((void**)&p_wih2h, g_wih2h);
    cudaGetSymbolAddress((void**)&p_whhh,  g_whhh);
    cudaGetSymbolAddress((void**)&p_gi,    g_gi);
    cudaGetSymbolAddress((void**)&p_bufAh, g_bufAh);
    cudaGetSymbolAddress((void**)&p_bufBh, g_bufBh);
    cudaGetSymbolAddress((void**)&p_hh,    g_hh);
    cudaGetSymbolAddress((void**)&p_gh,    g_gh);

    cudaFuncSetAttribute(gemm_f16_pipe, cudaFuncAttributeMaxDynamicSharedMemorySize, GEMM_SMEM);
    cudaFuncSetAttribute(gemm_f16_big,  cudaFuncAttributeMaxDynamicSharedMemorySize, BGEMM_SMEM);

    // ---- weight conversions ----
    {
        size_t n0 = (size_t)2 * G3 * INWP;
        cvt_wih0_kernel<<<(unsigned)((n0 + 255) / 256), 256>>>(w_ih[0]);
        size_t n1 = (size_t)2 * G3 * H2;
        cvt_half_kernel<<<1024, 256>>>((const float4*)w_ih[1], (uint2*)p_wih1h, n1 / 4);
        cvt_half_kernel<<<1024, 256>>>((const float4*)w_ih[2], (uint2*)p_wih2h, n1 / 4);
        size_t nh = (size_t)2 * G3 * HH;
        cvt_half_kernel<<<1024, 256>>>((const float4*)w_hh[0], (uint2*)(p_whhh + 0 * nh), nh / 4);
        cvt_half_kernel<<<1024, 256>>>((const float4*)w_hh[1], (uint2*)(p_whhh + 1 * nh), nh / 4);
        cvt_half_kernel<<<1024, 256>>>((const float4*)w_hh[2], (uint2*)(p_whhh + 2 * nh), nh / 4);
    }

    // ---- BatchNorm ----
    bn_stats_kernel<<<INW, 256>>>(x);
    {
        size_t n = (size_t)NT * INWP;
        bn_apply_kernel<<<(unsigned)((n + 255) / 256), 256>>>(x, bn_gamma, bn_beta);
    }

    const __half* layer_in[3]   = {p_xn, p_bufAh, p_bufBh};
    __half*       layer_outh[3] = {p_bufAh, p_bufBh, nullptr};
    float*        layer_outf[3] = {nullptr, nullptr, enc};
    const int     layer_k[3]    = {INWP, H2, H2};
    const __half* layer_wih[3]  = {p_wih0h, p_wih1h, p_wih2h};
    const size_t  nh = (size_t)2 * G3 * HH;

    for (int l = 0; l < 3; l++) {
        const int K = layer_k[l];

        // gi[d] = X @ w_ih[l][d]^T + b_ih[l][d]   — big-tile GEMM
        {
            dim3 grid(G3 / 256, NT / 128, 2);
            gemm_f16_big<<<grid, 256, BGEMM_SMEM>>>(layer_in[l], layer_wih[l], b_ih[l], p_gi,
                                                    NT, G3, K,
                                                    0L, (long)G3 * K, (long)G3, (long)NT * G3);
        }

        hzero_kernel<<<(2 * NB * HH) / 256, 256>>>();

        for (int t = 0; t < TT; t++) {
            // gh[d] = h[d] @ w_hh[l][d]^T + b_hh[l][d]
            dim3 grid(G3 / 128, NB / 128, 2);
            gemm_f16_pipe<<<grid, 256, GEMM_SMEM>>>(p_hh, p_whhh + (size_t)l * nh, b_hh[l], p_gh,
                                                    NB, G3, HH,
                                                    (long)NB * HH, (long)G3 * HH,
                                                    (long)G3, (long)NB * G3);

            gru_gate_kernel<<<512, 256>>>(layer_outh[l], layer_outf[l], t);
        }
    }

    fc_kernel<<<NB, 64>>>(enc, fc_w, fc_b, out);
}

// round 9
// speedup vs baseline: 1.4357x; 1.1276x over previous
#include <cuda_runtime.h>
#include <cuda_fp16.h>
#include <cstdint>
#include <math.h>

// ---------------------------------------------------------------------------
// Problem constants
// ---------------------------------------------------------------------------
#define NB   256
#define TT   64
#define INW  150
#define INWP 160
#define HH   1024
#define G3   (3*HH)
#define H2   (2*HH)
#define NT   (NB*TT)
#define NCLS 60

// ---------------------------------------------------------------------------
// Device scratch
// ---------------------------------------------------------------------------
__device__ __half g_xn   [(size_t)NT * INWP];
__device__ __half g_wih0h[(size_t)2 * G3 * INWP];
__device__ __half g_wih1h[(size_t)2 * G3 * H2];
__device__ __half g_wih2h[(size_t)2 * G3 * H2];
__device__ __half g_whhh [3][(size_t)2 * G3 * HH];
__device__ float  g_gi   [2][(size_t)NT * G3];
__device__ __half g_bufAh[(size_t)NT * H2];
__device__ __half g_bufBh[(size_t)NT * H2];
__device__ float  g_h    [2][(size_t)NB * HH];
__device__ __half g_hh   [2][(size_t)NB * HH];
__device__ float  g_gh2  [2][2][(size_t)NB * G3];   // [kslice][dir]
__device__ float  g_bn   [2 * INW];

// ---------------------------------------------------------------------------
// PTX helpers
// ---------------------------------------------------------------------------
__device__ __forceinline__ void mma_f16(float* d,
                                        uint32_t a0, uint32_t a1, uint32_t a2, uint32_t a3,
                                        uint32_t b0, uint32_t b1)
{
    asm volatile(
        "mma.sync.aligned.m16n8k16.row.col.f32.f16.f16.f32 "
        "{%0,%1,%2,%3}, {%4,%5,%6,%7}, {%8,%9}, {%0,%1,%2,%3};"
        : "+f"(d[0]), "+f"(d[1]), "+f"(d[2]), "+f"(d[3])
        : "r"(a0), "r"(a1), "r"(a2), "r"(a3), "r"(b0), "r"(b1));
}

__device__ __forceinline__ void ldsm_x4(uint32_t* r, uint32_t addr)
{
    asm volatile("ldmatrix.sync.aligned.m8n8.x4.shared.b16 {%0,%1,%2,%3}, [%4];"
                 : "=r"(r[0]), "=r"(r[1]), "=r"(r[2]), "=r"(r[3]) : "r"(addr));
}

__device__ __forceinline__ uint32_t smem_u32(const void* p) {
    uint32_t a;
    asm("{ .reg .u64 t; cvta.to.shared.u64 t, %1; cvt.u32.u64 %0, t; }" : "=r"(a) : "l"(p));
    return a;
}

__device__ __forceinline__ void cp_async16(uint32_t saddr, const void* gaddr)
{
    asm volatile("cp.async.cg.shared.global [%0], [%1], 16;" :: "r"(saddr), "l"(gaddr));
}
#define CP_COMMIT() asm volatile("cp.async.commit_group;" ::: "memory")
#define CP_WAIT(n)  asm volatile("cp.async.wait_group %0;" :: "n"(n) : "memory")

// ---------------------------------------------------------------------------
// Weight conversion fp32 -> fp16
// ---------------------------------------------------------------------------
__global__ void cvt_half_kernel(const float4* __restrict__ src, uint2* __restrict__ dst, size_t n4)
{
    for (size_t i = (size_t)blockIdx.x * blockDim.x + threadIdx.x; i < n4;
         i += (size_t)gridDim.x * blockDim.x) {
        float4 v = src[i];
        __half2 lo = __floats2half2_rn(v.x, v.y);
        __half2 hi = __floats2half2_rn(v.z, v.w);
        dst[i] = make_uint2(*(uint32_t*)&lo, *(uint32_t*)&hi);
    }
}

__global__ void cvt_wih0_kernel(const float* __restrict__ w)
{
    size_t i = (size_t)blockIdx.x * blockDim.x + threadIdx.x;
    if (i >= (size_t)2 * G3 * INWP) return;
    int c = (int)(i % INWP);
    size_t r = i / INWP;
    g_wih0h[i] = __float2half_rn((c < INW) ? w[r * INW + c] : 0.f);
}

// ---------------------------------------------------------------------------
// BatchNorm
// ---------------------------------------------------------------------------
__global__ void bn_stats_kernel(const float* __restrict__ x)
{
    int c = blockIdx.x;
    float s = 0.f, s2 = 0.f;
    for (int i = threadIdx.x; i < NT; i += blockDim.x) {
        float v = x[(size_t)i * INW + c];
        s += v; s2 += v * v;
    }
    __shared__ float sh0[256], sh1[256];
    sh0[threadIdx.x] = s; sh1[threadIdx.x] = s2;
    __syncthreads();
    for (int off = 128; off > 0; off >>= 1) {
        if (threadIdx.x < off) {
            sh0[threadIdx.x] += sh0[threadIdx.x + off];
            sh1[threadIdx.x] += sh1[threadIdx.x + off];
        }
        __syncthreads();
    }
    if (threadIdx.x == 0) {
        float mean = sh0[0] / (float)NT;
        float var  = sh1[0] / (float)NT - mean * mean;
        g_bn[c]       = mean;
        g_bn[INW + c] = rsqrtf(var + 1e-5f);
    }
}

__global__ void bn_apply_kernel(const float* __restrict__ x,
                                const float* __restrict__ gamma,
                                const float* __restrict__ beta)
{
    size_t i = (size_t)blockIdx.x * blockDim.x + threadIdx.x;
    if (i >= (size_t)NT * INWP) return;
    int c = (int)(i % INWP);
    size_t r = i / INWP;
    float v = 0.f;
    if (c < INW)
        v = (x[r * INW + c] - g_bn[c]) * g_bn[INW + c] * gamma[c] + beta[c];
    g_xn[i] = __float2half_rn(v);
}

// ---------------------------------------------------------------------------
// BIG input GEMM:  C[M,N] = A[M,K]*B[N,K]^T + bias[N]
// CTA 128x256x32, 8 warps (2M x 4N), warp tile 64x64.
// 3-stage cp.async, ldmatrix.x4, 80B row stride. ONE sync per k-tile.
// ---------------------------------------------------------------------------
#define ROWB    80
#define BSTAGES 3
#define B_ROWS  (128 + 256)
#define B_STG   (B_ROWS * ROWB)
#define BGEMM_SMEM (BSTAGES * B_STG)

__global__ __launch_bounds__(256, 1)
void gemm_f16_big(const __half* __restrict__ A, const __half* __restrict__ B,
                  const float* __restrict__ bias, float* __restrict__ C,
                  int M, int N, int K,
                  long sAz, long sBz, long sbz, long sCz)
{
    extern __shared__ __align__(16) char smem[];
    const uint32_t s0 = smem_u32(smem);

    const int bz = blockIdx.z;
    A    += (long)bz * sAz;
    B    += (long)bz * sBz;
    bias += (long)bz * sbz;
    C    += (long)bz * sCz;

    const int n0 = blockIdx.x * 256;
    const int m0 = blockIdx.y * 128;
    const int tid  = threadIdx.x;
    const int warp = tid >> 5;
    const int lane = tid & 31;
    const int wm = warp & 1;
    const int wn = warp >> 1;

    const uint32_t aoff = (uint32_t)(wm * 64 + (lane & 7) + ((lane >> 3) & 1) * 8) * ROWB
                        + ((lane >> 4) & 1) * 16;
    const uint32_t boff = (uint32_t)(128 + wn * 64 + (lane & 7) + ((lane >> 4) & 1) * 8) * ROWB
                        + ((lane >> 3) & 1) * 16;

    const char* gptr[6];
    uint32_t    soff[6];
    #pragma unroll
    for (int c = 0; c < 6; c++) {
        const int chunk = c * 256 + tid;
        const int row  = chunk >> 2;
        const int part = chunk & 3;
        if (row < 128) {
            gptr[c] = (const char*)(A + (long)(m0 + row) * K) + part * 16;
            soff[c] = (uint32_t)row * ROWB + part * 16;
        } else {
            gptr[c] = (const char*)(B + (long)(n0 + row - 128) * K) + part * 16;
            soff[c] = (uint32_t)row * ROWB + part * 16;
        }
    }

    float acc[4][8][4];
    #pragma unroll
    for (int i = 0; i < 4; i++)
        #pragma unroll
        for (int j = 0; j < 8; j++)
            #pragma unroll
            for (int q = 0; q < 4; q++) acc[i][j][q] = 0.f;

    const int KT = K >> 5;

    #pragma unroll
    for (int p = 0; p < BSTAGES - 1; p++) {
        #pragma unroll
        for (int c = 0; c < 6; c++)
            cp_async16(s0 + p * B_STG + soff[c], gptr[c] + p * 64);
        CP_COMMIT();
    }

    for (int kt = 0; kt < KT; kt++) {
        if (kt < KT - 1) { CP_WAIT(1); } else { CP_WAIT(0); }
        __syncthreads();

        if (kt + BSTAGES - 1 < KT) {
            const int nt = kt + BSTAGES - 1;
            const uint32_t sbase = s0 + (nt % BSTAGES) * B_STG;
            #pragma unroll
            for (int c = 0; c < 6; c++)
                cp_async16(sbase + soff[c], gptr[c] + nt * 64);
            CP_COMMIT();
        }

        const uint32_t stg = s0 + (kt % BSTAGES) * B_STG;
        const uint32_t aBase = stg + aoff;
        const uint32_t bBase = stg + boff;

        #pragma unroll
        for (int s = 0; s < 2; s++) {
            uint32_t a[4][4], b[4][4];
            #pragma unroll
            for (int i = 0; i < 4; i++)
                ldsm_x4(a[i], aBase + i * 16 * ROWB + s * 32);
            #pragma unroll
            for (int j2 = 0; j2 < 4; j2++)
                ldsm_x4(b[j2], bBase + j2 * 16 * ROWB + s * 32);

            #pragma unroll
            for (int i = 0; i < 4; i++)
                #pragma unroll
                for (int j2 = 0; j2 < 4; j2++) {
                    mma_f16(acc[i][2 * j2],     a[i][0], a[i][1], a[i][2], a[i][3],
                            b[j2][0], b[j2][1]);
                    mma_f16(acc[i][2 * j2 + 1], a[i][0], a[i][1], a[i][2], a[i][3],
                            b[j2][2], b[j2][3]);
                }
        }
        // no end-of-loop sync: stage is only rewritten after the NEXT top sync
    }

    #pragma unroll
    for (int i = 0; i < 4; i++) {
        const int row = m0 + wm * 64 + i * 16 + (lane >> 2);
        #pragma unroll
        for (int j = 0; j < 8; j++) {
            const int col = n0 + wn * 64 + j * 8 + (lane & 3) * 2;
            const float bx = __ldg(&bias[col]);
            const float by = __ldg(&bias[col + 1]);
            *(float2*)&C[(long)row * N + col] =
                make_float2(acc[i][j][0] + bx, acc[i][j][1] + by);
            *(float2*)&C[(long)(row + 8) * N + col] =
                make_float2(acc[i][j][2] + bx, acc[i][j][3] + by);
        }
    }
}

// ---------------------------------------------------------------------------
// Recurrent GEMM, split-K=2:  gh2[ks][d] = h[d][:, ks*512:(ks+1)*512] @ Wk^T
// CTA 128x128x32 over K=512.  Grid (24, 2, 4): z = d + 2*ks. No bias.
// 4-stage cp.async, ldmatrix, one sync per k-tile.
// ---------------------------------------------------------------------------
#define STAGES 4
#define STAGEB (128 * ROWB)
#define GEMM_SMEM (STAGES * 2 * STAGEB)
#define KSUB   512
#define R_KT   (KSUB / 32)

__global__ __launch_bounds__(256, 2)
void gemm_f16_rec(const __half* __restrict__ Wh)   // layer base [2][G3][HH]
{
    extern __shared__ __align__(16) char smem[];
    const uint32_t sA0 = smem_u32(smem);
    const uint32_t sB0 = sA0 + STAGES * STAGEB;

    const int d  = blockIdx.z & 1;
    const int ks = blockIdx.z >> 1;

    const __half* A = g_hh[d];                       // [NB][HH]
    const __half* B = Wh + (size_t)d * G3 * HH;      // [G3][HH]
    float* C = g_gh2[ks][d];                         // [NB][G3]

    const int n0 = blockIdx.x * 128;
    const int m0 = blockIdx.y * 128;
    const int tid  = threadIdx.x;
    const int warp = tid >> 5;
    const int lane = tid & 31;
    const int wm = warp & 1;
    const int wn = warp >> 1;

    const uint32_t aoff = (uint32_t)(wm * 64 + (lane & 7) + ((lane >> 3) & 1) * 8) * ROWB
                        + ((lane >> 4) & 1) * 16;
    const uint32_t boff = (uint32_t)(wn * 32 + (lane & 7) + ((lane >> 4) & 1) * 8) * ROWB
                        + ((lane >> 3) & 1) * 16;

    const int crow = tid >> 1;
    const int chal = tid & 1;
    const char* Ag = (const char*)(A + (long)(m0 + crow) * HH + ks * KSUB) + chal * 32;
    const char* Bg = (const char*)(B + (long)(n0 + crow) * HH + ks * KSUB) + chal * 32;
    const uint32_t sArow = sA0 + crow * ROWB + chal * 32;
    const uint32_t sBrow = sB0 + crow * ROWB + chal * 32;

    float acc[4][4][4];
    #pragma unroll
    for (int i = 0; i < 4; i++)
        #pragma unroll
        for (int j = 0; j < 4; j++)
            #pragma unroll
            for (int q = 0; q < 4; q++) acc[i][j][q] = 0.f;

    #pragma unroll
    for (int p = 0; p < STAGES - 1; p++) {
        const char* ag = Ag + p * 64;
        const char* bg = Bg + p * 64;
        const uint32_t sa = sArow + p * STAGEB;
        const uint32_t sb = sBrow + p * STAGEB;
        cp_async16(sa, ag);  cp_async16(sa + 16, ag + 16);
        cp_async16(sb, bg);  cp_async16(sb + 16, bg + 16);
        CP_COMMIT();
    }

    for (int kt = 0; kt < R_KT; kt++) {
        if      (kt <= R_KT - 3) { CP_WAIT(2); }
        else if (kt == R_KT - 2) { CP_WAIT(1); }
        else                     { CP_WAIT(0); }
        __syncthreads();

        if (kt + STAGES - 1 < R_KT) {
            const int nt = kt + STAGES - 1;
            const int sb_ = nt & 3;
            const char* ag = Ag + nt * 64;
            const char* bg = Bg + nt * 64;
            const uint32_t sa = sArow + sb_ * STAGEB;
            const uint32_t sbm = sBrow + sb_ * STAGEB;
            cp_async16(sa, ag);   cp_async16(sa + 16, ag + 16);
            cp_async16(sbm, bg);  cp_async16(sbm + 16, bg + 16);
            CP_COMMIT();
        }

        const int buf = kt & 3;
        const uint32_t aBase = sA0 + buf * STAGEB + aoff;
        const uint32_t bBase = sB0 + buf * STAGEB + boff;

        #pragma unroll
        for (int s = 0; s < 2; s++) {
            uint32_t a[4][4], b[2][4];
            #pragma unroll
            for (int i = 0; i < 4; i++)
                ldsm_x4(a[i], aBase + i * 16 * ROWB + s * 32);
            #pragma unroll
            for (int j2 = 0; j2 < 2; j2++)
                ldsm_x4(b[j2], bBase + j2 * 16 * ROWB + s * 32);

            #pragma unroll
            for (int i = 0; i < 4; i++)
                #pragma unroll
                for (int j2 = 0; j2 < 2; j2++) {
                    mma_f16(acc[i][2 * j2],     a[i][0], a[i][1], a[i][2], a[i][3],
                            b[j2][0], b[j2][1]);
                    mma_f16(acc[i][2 * j2 + 1], a[i][0], a[i][1], a[i][2], a[i][3],
                            b[j2][2], b[j2][3]);
                }
        }
        // no end-of-loop sync
    }

    #pragma unroll
    for (int i = 0; i < 4; i++) {
        const int row = m0 + wm * 64 + i * 16 + (lane >> 2);
        #pragma unroll
        for (int j = 0; j < 4; j++) {
            const int col = n0 + wn * 32 + j * 8 + (lane & 3) * 2;
            *(float2*)&C[(long)row * G3 + col] =
                make_float2(acc[i][j][0], acc[i][j][1]);
            *(float2*)&C[(long)(row + 8) * G3 + col] =
                make_float2(acc[i][j][2], acc[i][j][3]);
        }
    }
}

// ---------------------------------------------------------------------------
// hidden state zero
// ---------------------------------------------------------------------------
__global__ void hzero_kernel()
{
    size_t i = (size_t)blockIdx.x * blockDim.x + threadIdx.x;
    if (i < (size_t)2 * NB * HH) {
        ((float*)g_h)[i] = 0.f;
        ((__half*)g_hh)[i] = __float2half_rn(0.f);
    }
}

// ---------------------------------------------------------------------------
// GRU gate elementwise: gh = gh2[0] + gh2[1] + b_hh
// ---------------------------------------------------------------------------
__device__ __forceinline__ float4 add4(float4 a, float4 b, float4 c) {
    return make_float4(a.x + b.x + c.x, a.y + b.y + c.y,
                       a.z + b.z + c.z, a.w + b.w + c.w);
}

__global__ void gru_gate_kernel(__half* __restrict__ out_h, float* __restrict__ out_f,
                                const float* __restrict__ bhh, int t)
{
    int idx = blockIdx.x * blockDim.x + threadIdx.x;
    if (idx >= 2 * NB * HH / 4) return;
    int d   = idx >> 16;
    int rem = idx & 65535;
    int n   = rem >> 8;
    int jq  = rem & 255;

    const float4* gi = (const float4*)(g_gi[d]    + (size_t)(n * TT + t) * G3);
    const float4* g0 = (const float4*)(g_gh2[0][d] + (size_t)n * G3);
    const float4* g1 = (const float4*)(g_gh2[1][d] + (size_t)n * G3);
    const float4* bb = (const float4*)(bhh + (size_t)d * G3);

    float4 ir = gi[jq],       hr = add4(g0[jq],       g1[jq],       __ldg(&bb[jq]));
    float4 iz = gi[256 + jq], hz = add4(g0[256 + jq], g1[256 + jq], __ldg(&bb[256 + jq]));
    float4 in = gi[512 + jq], hn = add4(g0[512 + jq], g1[512 + jq], __ldg(&bb[512 + jq]));

    float4* hp = (float4*)(g_h[d] + (size_t)n * HH) + jq;
    float4 ho = *hp;
    float4 hv;

    {
        float r = 1.f / (1.f + __expf(-(ir.x + hr.x)));
        float z = 1.f / (1.f + __expf(-(iz.x + hz.x)));
        float nn = tanhf(in.x + r * hn.x);
        hv.x = (1.f - z) * nn + z * ho.x;
    }
    {
        float r = 1.f / (1.f + __expf(-(ir.y + hr.y)));
        float z = 1.f / (1.f + __expf(-(iz.y + hz.y)));
        float nn = tanhf(in.y + r * hn.y);
        hv.y = (1.f - z) * nn + z * ho.y;
    }
    {
        float r = 1.f / (1.f + __expf(-(ir.z + hr.z)));
        float z = 1.f / (1.f + __expf(-(iz.z + hz.z)));
        float nn = tanhf(in.z + r * hn.z);
        hv.z = (1.f - z) * nn + z * ho.z;
    }
    {
        float r = 1.f / (1.f + __expf(-(ir.w + hr.w)));
        float z = 1.f / (1.f + __expf(-(iz.w + hz.w)));
        float nn = tanhf(in.w + r * hn.w);
        hv.w = (1.f - z) * nn + z * ho.w;
    }

    *hp = hv;

    __half2 h01 = __floats2half2_rn(hv.x, hv.y);
    __half2 h23 = __floats2half2_rn(hv.z, hv.w);
    __half2* hhp = (__half2*)(g_hh[d] + (size_t)n * HH + 4 * jq);
    hhp[0] = h01; hhp[1] = h23;

    size_t ob = (size_t)(n * TT + t) * H2 + (size_t)d * HH + 4 * jq;
    if (out_f) {
        *(float4*)(out_f + ob) = hv;
    } else {
        __half2* op = (__half2*)(out_h + ob);
        op[0] = h01; op[1] = h23;
    }
}

// ---------------------------------------------------------------------------
// FC head
// ---------------------------------------------------------------------------
__global__ void fc_kernel(const float* __restrict__ enc,
                          const float* __restrict__ fc_w,
                          const float* __restrict__ fc_b,
                          float* __restrict__ out)
{
    int n = blockIdx.x;
    int c = threadIdx.x;
    if (c >= NCLS) return;
    const float* h = enc + ((size_t)n * TT + (TT - 1)) * H2;
    const float* w = fc_w + (size_t)c * H2;
    float s = 0.f;
    #pragma unroll 8
    for (int k = 0; k < H2; k++) s += h[k] * w[k];
    out[n * NCLS + c] = s + fc_b[c];
}

// ---------------------------------------------------------------------------
// Orchestration
// ---------------------------------------------------------------------------
extern "C" void kernel_launch(void* const* d_in, const int* in_sizes, int n_in,
                              void* d_out, int out_size)
{
    const float* x        = (const float*)d_in[0];
    const float* bn_gamma = (const float*)d_in[1];
    const float* bn_beta  = (const float*)d_in[2];
    const float* w_ih[3]  = {(const float*)d_in[3],  (const float*)d_in[7],  (const float*)d_in[11]};
    const float* w_hh[3]  = {(const float*)d_in[4],  (const float*)d_in[8],  (const float*)d_in[12]};
    const float* b_ih[3]  = {(const float*)d_in[5],  (const float*)d_in[9],  (const float*)d_in[13]};
    const float* b_hh[3]  = {(const float*)d_in[6],  (const float*)d_in[10], (const float*)d_in[14]};
    const float* fc_w     = (const float*)d_in[15];
    const float* fc_b     = (const float*)d_in[16];

    float* out = (float*)d_out;
    float* enc = out + (size_t)NB * NCLS;

    __half *p_xn, *p_wih0h, *p_wih1h, *p_wih2h, *p_whhh, *p_bufAh, *p_bufBh;
    cudaGetSymbolAddress((void**)&p_xn,    g_xn);
    cudaGetSymbolAddress((void**)&p_wih0h, g_wih0h);
    cudaGetSymbolAddress((void**)&p_wih1h, g_wih1h);
    cudaGetSymbolAddress((void**)&p_wih2h, g_wih2h);
    cudaGetSymbolAddress((void**)&p_whhh,  g_whhh);
    float* p_gi;
    cudaGetSymbolAddress((void**)&p_gi,    g_gi);
    cudaGetSymbolAddress((void**)&p_bufAh, g_bufAh);
    cudaGetSymbolAddress((void**)&p_bufBh, g_bufBh);

    cudaFuncSetAttribute(gemm_f16_rec, cudaFuncAttributeMaxDynamicSharedMemorySize, GEMM_SMEM);
    cudaFuncSetAttribute(gemm_f16_big, cudaFuncAttributeMaxDynamicSharedMemorySize, BGEMM_SMEM);

    // ---- weight conversions ----
    {
        size_t n0 = (size_t)2 * G3 * INWP;
        cvt_wih0_kernel<<<(unsigned)((n0 + 255) / 256), 256>>>(w_ih[0]);
        size_t n1 = (size_t)2 * G3 * H2;
        cvt_half_kernel<<<1024, 256>>>((const float4*)w_ih[1], (uint2*)p_wih1h, n1 / 4);
        cvt_half_kernel<<<1024, 256>>>((const float4*)w_ih[2], (uint2*)p_wih2h, n1 / 4);
        size_t nh = (size_t)2 * G3 * HH;
        cvt_half_kernel<<<1024, 256>>>((const float4*)w_hh[0], (uint2*)(p_whhh + 0 * nh), nh / 4);
        cvt_half_kernel<<<1024, 256>>>((const float4*)w_hh[1], (uint2*)(p_whhh + 1 * nh), nh / 4);
        cvt_half_kernel<<<1024, 256>>>((const float4*)w_hh[2], (uint2*)(p_whhh + 2 * nh), nh / 4);
    }

    // ---- BatchNorm ----
    bn_stats_kernel<<<INW, 256>>>(x);
    {
        size_t n = (size_t)NT * INWP;
        bn_apply_kernel<<<(unsigned)((n + 255) / 256), 256>>>(x, bn_gamma, bn_beta);
    }

    const __half* layer_in[3]   = {p_xn, p_bufAh, p_bufBh};
    __half*       layer_outh[3] = {p_bufAh, p_bufBh, nullptr};
    float*        layer_outf[3] = {nullptr, nullptr, enc};
    const int     layer_k[3]    = {INWP, H2, H2};
    const __half* layer_wih[3]  = {p_wih0h, p_wih1h, p_wih2h};
    const size_t  nh = (size_t)2 * G3 * HH;

    for (int l = 0; l < 3; l++) {
        const int K = layer_k[l];

        // gi[d] = X @ w_ih[l][d]^T + b_ih[l][d]
        {
            dim3 grid(G3 / 256, NT / 128, 2);
            gemm_f16_big<<<grid, 256, BGEMM_SMEM>>>(layer_in[l], layer_wih[l], b_ih[l], p_gi,
                                                    NT, G3, K,
                                                    0L, (long)G3 * K, (long)G3, (long)NT * G3);
        }

        hzero_kernel<<<(2 * NB * HH) / 256, 256>>>();

        for (int t = 0; t < TT; t++) {
            dim3 grid(G3 / 128, NB / 128, 4);   // z: d + 2*kslice
            gemm_f16_rec<<<grid, 256, GEMM_SMEM>>>(p_whhh + (size_t)l * nh);
            gru_gate_kernel<<<512, 256>>>(layer_outh[l], layer_outf[l], b_hh[l], t);
        }
    }

    fc_kernel<<<NB, 64>>>(enc, fc_w, fc_b, out);
}

// round 10
// speedup vs baseline: 1.5156x; 1.0557x over previous
#include <cuda_runtime.h>
#include <cuda_fp16.h>
#include <cstdint>
#include <math.h>

// ---------------------------------------------------------------------------
// Problem constants
// ---------------------------------------------------------------------------
#define NB   256
#define TT   64
#define INW  150
#define INWP 160
#define HH   1024
#define G3   (3*HH)
#define H2   (2*HH)
#define NT   (NB*TT)
#define NCLS 60

// ---------------------------------------------------------------------------
// Device scratch
// ---------------------------------------------------------------------------
__device__ __half g_xn   [(size_t)NT * INWP];
__device__ __half g_wih0h[(size_t)2 * G3 * INWP];
__device__ __half g_wih1h[(size_t)2 * G3 * H2];
__device__ __half g_wih2h[(size_t)2 * G3 * H2];
__device__ __half g_whhh [3][(size_t)2 * G3 * HH];
__device__ float  g_gi   [2][(size_t)NT * G3];
__device__ __half g_bufAh[(size_t)NT * H2];
__device__ __half g_bufBh[(size_t)NT * H2];
__device__ float  g_h    [2][(size_t)NB * HH];
__device__ __half g_hh   [2][(size_t)NB * HH];
__device__ float  g_gh3  [3][2][(size_t)NB * G3];   // [kslice][dir]
__device__ float  g_bn   [2 * INW];

// ---------------------------------------------------------------------------
// PTX helpers
// ---------------------------------------------------------------------------
__device__ __forceinline__ void mma_f16(float* d,
                                        uint32_t a0, uint32_t a1, uint32_t a2, uint32_t a3,
                                        uint32_t b0, uint32_t b1)
{
    asm volatile(
        "mma.sync.aligned.m16n8k16.row.col.f32.f16.f16.f32 "
        "{%0,%1,%2,%3}, {%4,%5,%6,%7}, {%8,%9}, {%0,%1,%2,%3};"
        : "+f"(d[0]), "+f"(d[1]), "+f"(d[2]), "+f"(d[3])
        : "r"(a0), "r"(a1), "r"(a2), "r"(a3), "r"(b0), "r"(b1));
}

__device__ __forceinline__ void ldsm_x4(uint32_t* r, uint32_t addr)
{
    asm volatile("ldmatrix.sync.aligned.m8n8.x4.shared.b16 {%0,%1,%2,%3}, [%4];"
                 : "=r"(r[0]), "=r"(r[1]), "=r"(r[2]), "=r"(r[3]) : "r"(addr));
}

__device__ __forceinline__ uint32_t smem_u32(const void* p) {
    uint32_t a;
    asm("{ .reg .u64 t; cvta.to.shared.u64 t, %1; cvt.u32.u64 %0, t; }" : "=r"(a) : "l"(p));
    return a;
}

__device__ __forceinline__ void cp_async16(uint32_t saddr, const void* gaddr)
{
    asm volatile("cp.async.cg.shared.global [%0], [%1], 16;" :: "r"(saddr), "l"(gaddr));
}
#define CP_COMMIT() asm volatile("cp.async.commit_group;" ::: "memory")
#define CP_WAIT(n)  asm volatile("cp.async.wait_group %0;" :: "n"(n) : "memory")

// ---------------------------------------------------------------------------
// Weight conversion fp32 -> fp16
// ---------------------------------------------------------------------------
__global__ void cvt_half_kernel(const float4* __restrict__ src, uint2* __restrict__ dst, size_t n4)
{
    for (size_t i = (size_t)blockIdx.x * blockDim.x + threadIdx.x; i < n4;
         i += (size_t)gridDim.x * blockDim.x) {
        float4 v = src[i];
        __half2 lo = __floats2half2_rn(v.x, v.y);
        __half2 hi = __floats2half2_rn(v.z, v.w);
        dst[i] = make_uint2(*(uint32_t*)&lo, *(uint32_t*)&hi);
    }
}

__global__ void cvt_wih0_kernel(const float* __restrict__ w)
{
    size_t i = (size_t)blockIdx.x * blockDim.x + threadIdx.x;
    if (i >= (size_t)2 * G3 * INWP) return;
    int c = (int)(i % INWP);
    size_t r = i / INWP;
    g_wih0h[i] = __float2half_rn((c < INW) ? w[r * INW + c] : 0.f);
}

// ---------------------------------------------------------------------------
// BatchNorm
// ---------------------------------------------------------------------------
__global__ void bn_stats_kernel(const float* __restrict__ x)
{
    int c = blockIdx.x;
    float s = 0.f, s2 = 0.f;
    for (int i = threadIdx.x; i < NT; i += blockDim.x) {
        float v = x[(size_t)i * INW + c];
        s += v; s2 += v * v;
    }
    __shared__ float sh0[256], sh1[256];
    sh0[threadIdx.x] = s; sh1[threadIdx.x] = s2;
    __syncthreads();
    for (int off = 128; off > 0; off >>= 1) {
        if (threadIdx.x < off) {
            sh0[threadIdx.x] += sh0[threadIdx.x + off];
            sh1[threadIdx.x] += sh1[threadIdx.x + off];
        }
        __syncthreads();
    }
    if (threadIdx.x == 0) {
        float mean = sh0[0] / (float)NT;
        float var  = sh1[0] / (float)NT - mean * mean;
        g_bn[c]       = mean;
        g_bn[INW + c] = rsqrtf(var + 1e-5f);
    }
}

__global__ void bn_apply_kernel(const float* __restrict__ x,
                                const float* __restrict__ gamma,
                                const float* __restrict__ beta)
{
    size_t i = (size_t)blockIdx.x * blockDim.x + threadIdx.x;
    if (i >= (size_t)NT * INWP) return;
    int c = (int)(i % INWP);
    size_t r = i / INWP;
    float v = 0.f;
    if (c < INW)
        v = (x[r * INW + c] - g_bn[c]) * g_bn[INW + c] * gamma[c] + beta[c];
    g_xn[i] = __float2half_rn(v);
}

// ---------------------------------------------------------------------------
// BIG input GEMM:  C[M,N] = A[M,K]*B[N,K]^T + bias[N]
// CTA 128x256x32, 8 warps, warp tile 64x64, 3-stage cp.async, ldmatrix.
// ---------------------------------------------------------------------------
#define ROWB    80
#define BSTAGES 3
#define B_ROWS  (128 + 256)
#define B_STG   (B_ROWS * ROWB)
#define BGEMM_SMEM (BSTAGES * B_STG)

__global__ __launch_bounds__(256, 1)
void gemm_f16_big(const __half* __restrict__ A, const __half* __restrict__ B,
                  const float* __restrict__ bias, float* __restrict__ C,
                  int M, int N, int K,
                  long sAz, long sBz, long sbz, long sCz)
{
    extern __shared__ __align__(16) char smem[];
    const uint32_t s0 = smem_u32(smem);

    const int bz = blockIdx.z;
    A    += (long)bz * sAz;
    B    += (long)bz * sBz;
    bias += (long)bz * sbz;
    C    += (long)bz * sCz;

    const int n0 = blockIdx.x * 256;
    const int m0 = blockIdx.y * 128;
    const int tid  = threadIdx.x;
    const int warp = tid >> 5;
    const int lane = tid & 31;
    const int wm = warp & 1;
    const int wn = warp >> 1;

    const uint32_t aoff = (uint32_t)(wm * 64 + (lane & 7) + ((lane >> 3) & 1) * 8) * ROWB
                        + ((lane >> 4) & 1) * 16;
    const uint32_t boff = (uint32_t)(128 + wn * 64 + (lane & 7) + ((lane >> 4) & 1) * 8) * ROWB
                        + ((lane >> 3) & 1) * 16;

    const char* gptr[6];
    uint32_t    soff[6];
    #pragma unroll
    for (int c = 0; c < 6; c++) {
        const int chunk = c * 256 + tid;
        const int row  = chunk >> 2;
        const int part = chunk & 3;
        if (row < 128) {
            gptr[c] = (const char*)(A + (long)(m0 + row) * K) + part * 16;
            soff[c] = (uint32_t)row * ROWB + part * 16;
        } else {
            gptr[c] = (const char*)(B + (long)(n0 + row - 128) * K) + part * 16;
            soff[c] = (uint32_t)row * ROWB + part * 16;
        }
    }

    float acc[4][8][4];
    #pragma unroll
    for (int i = 0; i < 4; i++)
        #pragma unroll
        for (int j = 0; j < 8; j++)
            #pragma unroll
            for (int q = 0; q < 4; q++) acc[i][j][q] = 0.f;

    const int KT = K >> 5;

    #pragma unroll
    for (int p = 0; p < BSTAGES - 1; p++) {
        #pragma unroll
        for (int c = 0; c < 6; c++)
            cp_async16(s0 + p * B_STG + soff[c], gptr[c] + p * 64);
        CP_COMMIT();
    }

    for (int kt = 0; kt < KT; kt++) {
        if (kt < KT - 1) { CP_WAIT(1); } else { CP_WAIT(0); }
        __syncthreads();

        if (kt + BSTAGES - 1 < KT) {
            const int nt = kt + BSTAGES - 1;
            const uint32_t sbase = s0 + (nt % BSTAGES) * B_STG;
            #pragma unroll
            for (int c = 0; c < 6; c++)
                cp_async16(sbase + soff[c], gptr[c] + nt * 64);
            CP_COMMIT();
        }

        const uint32_t stg = s0 + (kt % BSTAGES) * B_STG;
        const uint32_t aBase = stg + aoff;
        const uint32_t bBase = stg + boff;

        #pragma unroll
        for (int s = 0; s < 2; s++) {
            uint32_t a[4][4], b[4][4];
            #pragma unroll
            for (int i = 0; i < 4; i++)
                ldsm_x4(a[i], aBase + i * 16 * ROWB + s * 32);
            #pragma unroll
            for (int j2 = 0; j2 < 4; j2++)
                ldsm_x4(b[j2], bBase + j2 * 16 * ROWB + s * 32);

            #pragma unroll
            for (int i = 0; i < 4; i++)
                #pragma unroll
                for (int j2 = 0; j2 < 4; j2++) {
                    mma_f16(acc[i][2 * j2],     a[i][0], a[i][1], a[i][2], a[i][3],
                            b[j2][0], b[j2][1]);
                    mma_f16(acc[i][2 * j2 + 1], a[i][0], a[i][1], a[i][2], a[i][3],
                            b[j2][2], b[j2][3]);
                }
        }
    }

    #pragma unroll
    for (int i = 0; i < 4; i++) {
        const int row = m0 + wm * 64 + i * 16 + (lane >> 2);
        #pragma unroll
        for (int j = 0; j < 8; j++) {
            const int col = n0 + wn * 64 + j * 8 + (lane & 3) * 2;
            const float bx = __ldg(&bias[col]);
            const float by = __ldg(&bias[col + 1]);
            *(float2*)&C[(long)row * N + col] =
                make_float2(acc[i][j][0] + bx, acc[i][j][1] + by);
            *(float2*)&C[(long)(row + 8) * N + col] =
                make_float2(acc[i][j][2] + bx, acc[i][j][3] + by);
        }
    }
}

// ---------------------------------------------------------------------------
// Recurrent GEMM, split-K=3 (balanced wave: 288 CTAs ~= 296 slots):
//   gh3[ks][d] = h[d][:, k0:k0+KT*32] @ Wh[d]^T   (slices of 352/352/320)
// CTA 128x128, grid (24, 2, 6): z = d + 2*ks.
// 4-stage cp.async, ldmatrix, one sync per k-tile.
// ---------------------------------------------------------------------------
#define STAGES 4
#define STAGEB (128 * ROWB)
#define GEMM_SMEM (STAGES * 2 * STAGEB)

__global__ __launch_bounds__(256, 2)
void gemm_f16_rec(const __half* __restrict__ Wh)   // layer base [2][G3][HH]
{
    extern __shared__ __align__(16) char smem[];
    const uint32_t sA0 = smem_u32(smem);
    const uint32_t sB0 = sA0 + STAGES * STAGEB;

    const int d  = blockIdx.z & 1;
    const int ks = blockIdx.z >> 1;           // 0,1,2
    const int kt0 = ks * 11;                  // start k32-tile: 0,11,22
    const int KT  = (ks < 2) ? 11 : 10;       // 11/11/10 tiles

    const __half* A = g_hh[d];                       // [NB][HH]
    const __half* B = Wh + (size_t)d * G3 * HH;      // [G3][HH]
    float* C = g_gh3[ks][d];                         // [NB][G3]

    const int n0 = blockIdx.x * 128;
    const int m0 = blockIdx.y * 128;
    const int tid  = threadIdx.x;
    const int warp = tid >> 5;
    const int lane = tid & 31;
    const int wm = warp & 1;
    const int wn = warp >> 1;

    const uint32_t aoff = (uint32_t)(wm * 64 + (lane & 7) + ((lane >> 3) & 1) * 8) * ROWB
                        + ((lane >> 4) & 1) * 16;
    const uint32_t boff = (uint32_t)(wn * 32 + (lane & 7) + ((lane >> 4) & 1) * 8) * ROWB
                        + ((lane >> 3) & 1) * 16;

    const int crow = tid >> 1;
    const int chal = tid & 1;
    const char* Ag = (const char*)(A + (long)(m0 + crow) * HH + kt0 * 32) + chal * 32;
    const char* Bg = (const char*)(B + (long)(n0 + crow) * HH + kt0 * 32) + chal * 32;
    const uint32_t sArow = sA0 + crow * ROWB + chal * 32;
    const uint32_t sBrow = sB0 + crow * ROWB + chal * 32;

    float acc[4][4][4];
    #pragma unroll
    for (int i = 0; i < 4; i++)
        #pragma unroll
        for (int j = 0; j < 4; j++)
            #pragma unroll
            for (int q = 0; q < 4; q++) acc[i][j][q] = 0.f;

    #pragma unroll
    for (int p = 0; p < STAGES - 1; p++) {
        const char* ag = Ag + p * 64;
        const char* bg = Bg + p * 64;
        const uint32_t sa = sArow + p * STAGEB;
        const uint32_t sb = sBrow + p * STAGEB;
        cp_async16(sa, ag);  cp_async16(sa + 16, ag + 16);
        cp_async16(sb, bg);  cp_async16(sb + 16, bg + 16);
        CP_COMMIT();
    }

    for (int kt = 0; kt < KT; kt++) {
        if      (kt <= KT - 3) { CP_WAIT(2); }
        else if (kt == KT - 2) { CP_WAIT(1); }
        else                   { CP_WAIT(0); }
        __syncthreads();

        if (kt + STAGES - 1 < KT) {
            const int nt = kt + STAGES - 1;
            const int sb_ = nt & 3;
            const char* ag = Ag + nt * 64;
            const char* bg = Bg + nt * 64;
            const uint32_t sa = sArow + sb_ * STAGEB;
            const uint32_t sbm = sBrow + sb_ * STAGEB;
            cp_async16(sa, ag);   cp_async16(sa + 16, ag + 16);
            cp_async16(sbm, bg);  cp_async16(sbm + 16, bg + 16);
            CP_COMMIT();
        }

        const int buf = kt & 3;
        const uint32_t aBase = sA0 + buf * STAGEB + aoff;
        const uint32_t bBase = sB0 + buf * STAGEB + boff;

        #pragma unroll
        for (int s = 0; s < 2; s++) {
            uint32_t a[4][4], b[2][4];
            #pragma unroll
            for (int i = 0; i < 4; i++)
                ldsm_x4(a[i], aBase + i * 16 * ROWB + s * 32);
            #pragma unroll
            for (int j2 = 0; j2 < 2; j2++)
                ldsm_x4(b[j2], bBase + j2 * 16 * ROWB + s * 32);

            #pragma unroll
            for (int i = 0; i < 4; i++)
                #pragma unroll
                for (int j2 = 0; j2 < 2; j2++) {
                    mma_f16(acc[i][2 * j2],     a[i][0], a[i][1], a[i][2], a[i][3],
                            b[j2][0], b[j2][1]);
                    mma_f16(acc[i][2 * j2 + 1], a[i][0], a[i][1], a[i][2], a[i][3],
                            b[j2][2], b[j2][3]);
                }
        }
    }

    #pragma unroll
    for (int i = 0; i < 4; i++) {
        const int row = m0 + wm * 64 + i * 16 + (lane >> 2);
        #pragma unroll
        for (int j = 0; j < 4; j++) {
            const int col = n0 + wn * 32 + j * 8 + (lane & 3) * 2;
            *(float2*)&C[(long)row * G3 + col] =
                make_float2(acc[i][j][0], acc[i][j][1]);
            *(float2*)&C[(long)(row + 8) * G3 + col] =
                make_float2(acc[i][j][2], acc[i][j][3]);
        }
    }
}

// ---------------------------------------------------------------------------
// hidden state zero
// ---------------------------------------------------------------------------
__global__ void hzero_kernel()
{
    size_t i = (size_t)blockIdx.x * blockDim.x + threadIdx.x;
    if (i < (size_t)2 * NB * HH) {
        ((float*)g_h)[i] = 0.f;
        ((__half*)g_hh)[i] = __float2half_rn(0.f);
    }
}

// ---------------------------------------------------------------------------
// GRU gate elementwise: gh = gh3[0] + gh3[1] + gh3[2] + b_hh
// ---------------------------------------------------------------------------
__device__ __forceinline__ float4 add4b(float4 a, float4 b, float4 c, float4 e) {
    return make_float4(a.x + b.x + c.x + e.x, a.y + b.y + c.y + e.y,
                       a.z + b.z + c.z + e.z, a.w + b.w + c.w + e.w);
}

__global__ __launch_bounds__(256)
void gru_gate_kernel(__half* __restrict__ out_h, float* __restrict__ out_f,
                     const float* __restrict__ bhh, int t)
{
    int idx = blockIdx.x * blockDim.x + threadIdx.x;
    if (idx >= 2 * NB * HH / 4) return;
    int d   = idx >> 16;
    int rem = idx & 65535;
    int n   = rem >> 8;
    int jq  = rem & 255;

    const float4* gi = (const float4*)(g_gi[d]     + (size_t)(n * TT + t) * G3);
    const float4* g0 = (const float4*)(g_gh3[0][d] + (size_t)n * G3);
    const float4* g1 = (const float4*)(g_gh3[1][d] + (size_t)n * G3);
    const float4* g2 = (const float4*)(g_gh3[2][d] + (size_t)n * G3);
    const float4* bb = (const float4*)(bhh + (size_t)d * G3);

    float4 ir = gi[jq],       hr = add4b(g0[jq],       g1[jq],       g2[jq],       __ldg(&bb[jq]));
    float4 iz = gi[256 + jq], hz = add4b(g0[256 + jq], g1[256 + jq], g2[256 + jq], __ldg(&bb[256 + jq]));
    float4 in = gi[512 + jq], hn = add4b(g0[512 + jq], g1[512 + jq], g2[512 + jq], __ldg(&bb[512 + jq]));

    float4* hp = (float4*)(g_h[d] + (size_t)n * HH) + jq;
    float4 ho = *hp;
    float4 hv;

    {
        float r = 1.f / (1.f + __expf(-(ir.x + hr.x)));
        float z = 1.f / (1.f + __expf(-(iz.x + hz.x)));
        float nn = tanhf(in.x + r * hn.x);
        hv.x = (1.f - z) * nn + z * ho.x;
    }
    {
        float r = 1.f / (1.f + __expf(-(ir.y + hr.y)));
        float z = 1.f / (1.f + __expf(-(iz.y + hz.y)));
        float nn = tanhf(in.y + r * hn.y);
        hv.y = (1.f - z) * nn + z * ho.y;
    }
    {
        float r = 1.f / (1.f + __expf(-(ir.z + hr.z)));
        float z = 1.f / (1.f + __expf(-(iz.z + hz.z)));
        float nn = tanhf(in.z + r * hn.z);
        hv.z = (1.f - z) * nn + z * ho.z;
    }
    {
        float r = 1.f / (1.f + __expf(-(ir.w + hr.w)));
        float z = 1.f / (1.f + __expf(-(iz.w + hz.w)));
        float nn = tanhf(in.w + r * hn.w);
        hv.w = (1.f - z) * nn + z * ho.w;
    }

    *hp = hv;

    __half2 h01 = __floats2half2_rn(hv.x, hv.y);
    __half2 h23 = __floats2half2_rn(hv.z, hv.w);
    __half2* hhp = (__half2*)(g_hh[d] + (size_t)n * HH + 4 * jq);
    hhp[0] = h01; hhp[1] = h23;

    size_t ob = (size_t)(n * TT + t) * H2 + (size_t)d * HH + 4 * jq;
    if (out_f) {
        *(float4*)(out_f + ob) = hv;
    } else {
        __half2* op = (__half2*)(out_h + ob);
        op[0] = h01; op[1] = h23;
    }
}

// ---------------------------------------------------------------------------
// FC head
// ---------------------------------------------------------------------------
__global__ void fc_kernel(const float* __restrict__ enc,
                          const float* __restrict__ fc_w,
                          const float* __restrict__ fc_b,
                          float* __restrict__ out)
{
    int n = blockIdx.x;
    int c = threadIdx.x;
    if (c >= NCLS) return;
    const float* h = enc + ((size_t)n * TT + (TT - 1)) * H2;
    const float* w = fc_w + (size_t)c * H2;
    float s = 0.f;
    #pragma unroll 8
    for (int k = 0; k < H2; k++) s += h[k] * w[k];
    out[n * NCLS + c] = s + fc_b[c];
}

// ---------------------------------------------------------------------------
// Orchestration
// ---------------------------------------------------------------------------
extern "C" void kernel_launch(void* const* d_in, const int* in_sizes, int n_in,
                              void* d_out, int out_size)
{
    const float* x        = (const float*)d_in[0];
    const float* bn_gamma = (const float*)d_in[1];
    const float* bn_beta  = (const float*)d_in[2];
    const float* w_ih[3]  = {(const float*)d_in[3],  (const float*)d_in[7],  (const float*)d_in[11]};
    const float* w_hh[3]  = {(const float*)d_in[4],  (const float*)d_in[8],  (const float*)d_in[12]};
    const float* b_ih[3]  = {(const float*)d_in[5],  (const float*)d_in[9],  (const float*)d_in[13]};
    const float* b_hh[3]  = {(const float*)d_in[6],  (const float*)d_in[10], (const float*)d_in[14]};
    const float* fc_w     = (const float*)d_in[15];
    const float* fc_b     = (const float*)d_in[16];

    float* out = (float*)d_out;
    float* enc = out + (size_t)NB * NCLS;

    __half *p_xn, *p_wih0h, *p_wih1h, *p_wih2h, *p_whhh, *p_bufAh, *p_bufBh;
    cudaGetSymbolAddress((void**)&p_xn,    g_xn);
    cudaGetSymbolAddress((void**)&p_wih0h, g_wih0h);
    cudaGetSymbolAddress((void**)&p_wih1h, g_wih1h);
    cudaGetSymbolAddress((void**)&p_wih2h, g_wih2h);
    cudaGetSymbolAddress((void**)&p_whhh,  g_whhh);
    float* p_gi;
    cudaGetSymbolAddress((void**)&p_gi,    g_gi);
    cudaGetSymbolAddress((void**)&p_bufAh, g_bufAh);
    cudaGetSymbolAddress((void**)&p_bufBh, g_bufBh);

    cudaFuncSetAttribute(gemm_f16_rec, cudaFuncAttributeMaxDynamicSharedMemorySize, GEMM_SMEM);
    cudaFuncSetAttribute(gemm_f16_big, cudaFuncAttributeMaxDynamicSharedMemorySize, BGEMM_SMEM);

    // ---- weight conversions ----
    {
        size_t n0 = (size_t)2 * G3 * INWP;
        cvt_wih0_kernel<<<(unsigned)((n0 + 255) / 256), 256>>>(w_ih[0]);
        size_t n1 = (size_t)2 * G3 * H2;
        cvt_half_kernel<<<1024, 256>>>((const float4*)w_ih[1], (uint2*)p_wih1h, n1 / 4);
        cvt_half_kernel<<<1024, 256>>>((const float4*)w_ih[2], (uint2*)p_wih2h, n1 / 4);
        size_t nh = (size_t)2 * G3 * HH;
        cvt_half_kernel<<<1024, 256>>>((const float4*)w_hh[0], (uint2*)(p_whhh + 0 * nh), nh / 4);
        cvt_half_kernel<<<1024, 256>>>((const float4*)w_hh[1], (uint2*)(p_whhh + 1 * nh), nh / 4);
        cvt_half_kernel<<<1024, 256>>>((const float4*)w_hh[2], (uint2*)(p_whhh + 2 * nh), nh / 4);
    }

    // ---- BatchNorm ----
    bn_stats_kernel<<<INW, 256>>>(x);
    {
        size_t n = (size_t)NT * INWP;
        bn_apply_kernel<<<(unsigned)((n + 255) / 256), 256>>>(x, bn_gamma, bn_beta);
    }

    const __half* layer_in[3]   = {p_xn, p_bufAh, p_bufBh};
    __half*       layer_outh[3] = {p_bufAh, p_bufBh, nullptr};
    float*        layer_outf[3] = {nullptr, nullptr, enc};
    const int     layer_k[3]    = {INWP, H2, H2};
    const __half* layer_wih[3]  = {p_wih0h, p_wih1h, p_wih2h};
    const size_t  nh = (size_t)2 * G3 * HH;

    for (int l = 0; l < 3; l++) {
        const int K = layer_k[l];

        // gi[d] = X @ w_ih[l][d]^T + b_ih[l][d]
        {
            dim3 grid(G3 / 256, NT / 128, 2);
            gemm_f16_big<<<grid, 256, BGEMM_SMEM>>>(layer_in[l], layer_wih[l], b_ih[l], p_gi,
                                                    NT, G3, K,
                                                    0L, (long)G3 * K, (long)G3, (long)NT * G3);
        }

        hzero_kernel<<<(2 * NB * HH) / 256, 256>>>();

        for (int t = 0; t < TT; t++) {
            dim3 grid(G3 / 128, NB / 128, 6);   // z: d + 2*kslice, kslice 0..2
            gemm_f16_rec<<<grid, 256, GEMM_SMEM>>>(p_whhh + (size_t)l * nh);
            gru_gate_kernel<<<512, 256>>>(layer_outh[l], layer_outf[l], b_hh[l], t);
        }
    }

    fc_kernel<<<NB, 64>>>(enc, fc_w, fc_b, out);
}